// round 3
// baseline (speedup 1.0000x reference)
#include <cuda_runtime.h>
#include <math.h>

#define N_NODES 100000
#define E_EDGES 800000
#define ET (E_EDGES + N_NODES)   // edges + self loops = 900000
#define IN_CH 128
#define HID 32
#define HEADS 8
#define C1 (HEADS * HID)          // 256
#define OUT_CH 40
#define NEG_SLOPE 0.2f

// ---------------- scratch (device globals; no allocation allowed) ----------
__device__ float g_xp1[N_NODES * C1];
__device__ float g_acc1[N_NODES * C1];
__device__ float g_h[N_NODES * C1];
__device__ float g_xp2[N_NODES * OUT_CH];
__device__ float g_acc2[N_NODES * OUT_CH];
__device__ float g_as1[N_NODES * HEADS];
__device__ float g_ad1[N_NODES * HEADS];
__device__ float g_m1[N_NODES * HEADS];
__device__ float g_z1[N_NODES * HEADS];
__device__ float g_as2[N_NODES];
__device__ float g_ad2[N_NODES];
__device__ float g_m2[N_NODES];
__device__ float g_z2[N_NODES];

__device__ __forceinline__ void atomicMaxF(float* addr, float val) {
    if (val >= 0.0f) atomicMax((int*)addr, __float_as_int(val));
    else             atomicMin((unsigned int*)addr, (unsigned int)__float_as_int(val));
}

__device__ __forceinline__ float leaky(float x) {
    return x > 0.0f ? x : NEG_SLOPE * x;
}

// ---------------- init ------------------------------------------------------
__global__ void init_kernel() {
    int stride = gridDim.x * blockDim.x;
    for (int i = blockIdx.x * blockDim.x + threadIdx.x; i < N_NODES * C1; i += stride) {
        g_acc1[i] = 0.0f;
        if (i < N_NODES * OUT_CH) g_acc2[i] = 0.0f;
        if (i < N_NODES * HEADS) { g_m1[i] = -INFINITY; g_z1[i] = 0.0f; }
        if (i < N_NODES)         { g_m2[i] = -INFINITY; g_z2[i] = 0.0f; }
    }
}

// ---------------- tiled SGEMM: C[M,Ncol] = A[M,K] @ B[K,Ncol] ---------------
// BM=BN=64, BK=16, 256 threads, 4x4 per thread.
__global__ void sgemm_kernel(const float* __restrict__ A, const float* __restrict__ B,
                             float* __restrict__ C, int M, int K, int Ncol) {
    __shared__ float As[16][64];
    __shared__ float Bs[16][64];

    const int tid = threadIdx.x;
    const int tx = tid & 15;           // 0..15 -> col group
    const int ty = tid >> 4;           // 0..15 -> row group
    const int rowBase = blockIdx.y * 64;
    const int colBase = blockIdx.x * 64;

    float acc[4][4];
#pragma unroll
    for (int i = 0; i < 4; i++)
#pragma unroll
        for (int j = 0; j < 4; j++) acc[i][j] = 0.0f;

    const int arow = tid >> 2;         // 0..63
    const int akq  = tid & 3;          // 0..3 (float4 within 16 k)
    const int bk   = tid >> 4;         // 0..15
    const int bcq  = tid & 15;         // 0..15 (float4 within 64 cols)

    for (int k0 = 0; k0 < K; k0 += 16) {
        // load A tile -> As[k][row]
        {
            float4 v = make_float4(0.f, 0.f, 0.f, 0.f);
            int gr = rowBase + arow;
            if (gr < M) v = *(const float4*)&A[(long)gr * K + k0 + akq * 4];
            As[akq * 4 + 0][arow] = v.x;
            As[akq * 4 + 1][arow] = v.y;
            As[akq * 4 + 2][arow] = v.z;
            As[akq * 4 + 3][arow] = v.w;
        }
        // load B tile -> Bs[k][col]
        {
            int gc = colBase + bcq * 4;
            float4 v;
            if (gc + 3 < Ncol) {
                v = *(const float4*)&B[(long)(k0 + bk) * Ncol + gc];
            } else {
                v.x = (gc + 0 < Ncol) ? B[(long)(k0 + bk) * Ncol + gc + 0] : 0.f;
                v.y = (gc + 1 < Ncol) ? B[(long)(k0 + bk) * Ncol + gc + 1] : 0.f;
                v.z = (gc + 2 < Ncol) ? B[(long)(k0 + bk) * Ncol + gc + 2] : 0.f;
                v.w = (gc + 3 < Ncol) ? B[(long)(k0 + bk) * Ncol + gc + 3] : 0.f;
            }
            *(float4*)&Bs[bk][bcq * 4] = v;
        }
        __syncthreads();

#pragma unroll
        for (int k = 0; k < 16; k++) {
            float4 a = *(const float4*)&As[k][ty * 4];
            float4 b = *(const float4*)&Bs[k][tx * 4];
            float av[4] = {a.x, a.y, a.z, a.w};
            float bv[4] = {b.x, b.y, b.z, b.w};
#pragma unroll
            for (int i = 0; i < 4; i++)
#pragma unroll
                for (int j = 0; j < 4; j++) acc[i][j] += av[i] * bv[j];
        }
        __syncthreads();
    }

#pragma unroll
    for (int i = 0; i < 4; i++) {
        int r = rowBase + ty * 4 + i;
        if (r >= M) continue;
#pragma unroll
        for (int j = 0; j < 4; j++) {
            int c = colBase + tx * 4 + j;
            if (c < Ncol) C[(long)r * Ncol + c] = acc[i][j];
        }
    }
}

// ---------------- attention coefficients, layer 1 (warp per node) -----------
__global__ void attn1_kernel(const float* __restrict__ att_src,
                             const float* __restrict__ att_dst) {
    int warp = (blockIdx.x * blockDim.x + threadIdx.x) >> 5;
    int lane = threadIdx.x & 31;
    if (warp >= N_NODES) return;
    const float* xp = &g_xp1[(long)warp * C1];
#pragma unroll
    for (int it = 0; it < 8; it++) {
        int c = it * 32 + lane;
        float v = xp[c];
        float ps = v * att_src[c];
        float pd = v * att_dst[c];
#pragma unroll
        for (int o = 16; o > 0; o >>= 1) {
            ps += __shfl_xor_sync(0xffffffffu, ps, o);
            pd += __shfl_xor_sync(0xffffffffu, pd, o);
        }
        if (lane == 0) {
            g_as1[warp * 8 + it] = ps;
            g_ad1[warp * 8 + it] = pd;
        }
    }
}

// ---------------- edge pass 1a: segment max (thread per edge) ---------------
__global__ void edge_max1_kernel(const int* __restrict__ ei) {
    int e = blockIdx.x * blockDim.x + threadIdx.x;
    if (e >= ET) return;
    int src, dst;
    if (e < E_EDGES) { src = ei[e]; dst = ei[E_EDGES + e]; }
    else             { src = dst = e - E_EDGES; }
    const float4 s0 = *(const float4*)&g_as1[src * 8];
    const float4 s1 = *(const float4*)&g_as1[src * 8 + 4];
    const float4 d0 = *(const float4*)&g_ad1[dst * 8];
    const float4 d1 = *(const float4*)&g_ad1[dst * 8 + 4];
    float ls[8] = {s0.x + d0.x, s0.y + d0.y, s0.z + d0.z, s0.w + d0.w,
                   s1.x + d1.x, s1.y + d1.y, s1.z + d1.z, s1.w + d1.w};
#pragma unroll
    for (int h = 0; h < 8; h++) atomicMaxF(&g_m1[dst * 8 + h], leaky(ls[h]));
}

// ---------------- edge pass 1b: exp + weighted aggregate (warp per edge) ----
__global__ void edge_sum1_kernel(const int* __restrict__ ei) {
    int warp = (blockIdx.x * blockDim.x + threadIdx.x) >> 5;
    int lane = threadIdx.x & 31;
    if (warp >= ET) return;
    int src, dst;
    if (warp < E_EDGES) { src = ei[warp]; dst = ei[E_EDGES + warp]; }
    else                { src = dst = warp - E_EDGES; }
    float p = 0.0f;
    if (lane < 8) {
        float l = leaky(g_as1[src * 8 + lane] + g_ad1[dst * 8 + lane]);
        p = __expf(l - g_m1[dst * 8 + lane]);
        atomicAdd(&g_z1[dst * 8 + lane], p);
    }
    const float* xs = &g_xp1[(long)src * C1];
    float* ad = &g_acc1[(long)dst * C1];
#pragma unroll
    for (int h = 0; h < 8; h++) {
        float ph = __shfl_sync(0xffffffffu, p, h);
        atomicAdd(&ad[h * 32 + lane], ph * xs[h * 32 + lane]);
    }
}

// ---------------- finalize layer 1: divide, bias, relu ----------------------
__global__ void finalize1_kernel(const float* __restrict__ b1) {
    int stride = gridDim.x * blockDim.x;
    for (int i = blockIdx.x * blockDim.x + threadIdx.x; i < N_NODES * C1; i += stride) {
        int n = i >> 8;
        int c = i & 255;
        float z = g_z1[n * 8 + (c >> 5)] + 1e-16f;
        float v = g_acc1[i] / z + b1[c];
        g_h[i] = v > 0.0f ? v : 0.0f;
    }
}

// ---------------- attention coefficients, layer 2 (warp per node) -----------
__global__ void attn2_kernel(const float* __restrict__ att_src,
                             const float* __restrict__ att_dst) {
    int warp = (blockIdx.x * blockDim.x + threadIdx.x) >> 5;
    int lane = threadIdx.x & 31;
    if (warp >= N_NODES) return;
    const float* xp = &g_xp2[(long)warp * OUT_CH];
    float v = xp[lane];
    float s = v * att_src[lane];
    float d = v * att_dst[lane];
    if (lane < 8) {
        float v2 = xp[32 + lane];
        s += v2 * att_src[32 + lane];
        d += v2 * att_dst[32 + lane];
    }
#pragma unroll
    for (int o = 16; o > 0; o >>= 1) {
        s += __shfl_xor_sync(0xffffffffu, s, o);
        d += __shfl_xor_sync(0xffffffffu, d, o);
    }
    if (lane == 0) { g_as2[warp] = s; g_ad2[warp] = d; }
}

__global__ void edge_max2_kernel(const int* __restrict__ ei) {
    int e = blockIdx.x * blockDim.x + threadIdx.x;
    if (e >= ET) return;
    int src, dst;
    if (e < E_EDGES) { src = ei[e]; dst = ei[E_EDGES + e]; }
    else             { src = dst = e - E_EDGES; }
    atomicMaxF(&g_m2[dst], leaky(g_as2[src] + g_ad2[dst]));
}

__global__ void edge_sum2_kernel(const int* __restrict__ ei) {
    int warp = (blockIdx.x * blockDim.x + threadIdx.x) >> 5;
    int lane = threadIdx.x & 31;
    if (warp >= ET) return;
    int src, dst;
    if (warp < E_EDGES) { src = ei[warp]; dst = ei[E_EDGES + warp]; }
    else                { src = dst = warp - E_EDGES; }
    float p = __expf(leaky(g_as2[src] + g_ad2[dst]) - g_m2[dst]);
    if (lane == 0) atomicAdd(&g_z2[dst], p);
    const float* xs = &g_xp2[(long)src * OUT_CH];
    float* ad = &g_acc2[(long)dst * OUT_CH];
    atomicAdd(&ad[lane], p * xs[lane]);
    if (lane < 8) atomicAdd(&ad[32 + lane], p * xs[32 + lane]);
}

// ---------------- finalize layer 2 + log_softmax (warp per node) ------------
__global__ void final_kernel(const float* __restrict__ b2, float* __restrict__ out) {
    int warp = (blockIdx.x * blockDim.x + threadIdx.x) >> 5;
    int lane = threadIdx.x & 31;
    if (warp >= N_NODES) return;
    float z = g_z2[warp] + 1e-16f;
    const float* ac = &g_acc2[(long)warp * OUT_CH];
    float x1 = ac[lane] / z + b2[lane];
    float x2 = (lane < 8) ? (ac[32 + lane] / z + b2[32 + lane]) : -INFINITY;
    float mx = fmaxf(x1, x2);
#pragma unroll
    for (int o = 16; o > 0; o >>= 1) mx = fmaxf(mx, __shfl_xor_sync(0xffffffffu, mx, o));
    float se = __expf(x1 - mx) + ((lane < 8) ? __expf(x2 - mx) : 0.0f);
#pragma unroll
    for (int o = 16; o > 0; o >>= 1) se += __shfl_xor_sync(0xffffffffu, se, o);
    float lse = mx + logf(se);
    out[(long)warp * OUT_CH + lane] = x1 - lse;
    if (lane < 8) out[(long)warp * OUT_CH + 32 + lane] = x2 - lse;
}

// ---------------- launch ----------------------------------------------------
extern "C" void kernel_launch(void* const* d_in, const int* in_sizes, int n_in,
                              void* d_out, int out_size) {
    const float* x        = (const float*)d_in[0];
    const int*   ei       = (const int*)d_in[1];     // int32: JAX demotes int64
    const float* W1       = (const float*)d_in[2];
    const float* att_src1 = (const float*)d_in[3];
    const float* att_dst1 = (const float*)d_in[4];
    const float* b1       = (const float*)d_in[5];
    const float* W2       = (const float*)d_in[6];
    const float* att_src2 = (const float*)d_in[7];
    const float* att_dst2 = (const float*)d_in[8];
    const float* b2       = (const float*)d_in[9];
    float*       out      = (float*)d_out;

    float* xp1 = nullptr; float* h = nullptr; float* xp2 = nullptr;
    cudaGetSymbolAddress((void**)&xp1, g_xp1);
    cudaGetSymbolAddress((void**)&h,   g_h);
    cudaGetSymbolAddress((void**)&xp2, g_xp2);

    init_kernel<<<4096, 256>>>();

    // layer 1
    {
        dim3 grid((C1 + 63) / 64, (N_NODES + 63) / 64);
        sgemm_kernel<<<grid, 256>>>(x, W1, xp1, N_NODES, IN_CH, C1);
    }
    attn1_kernel<<<(N_NODES * 32 + 255) / 256, 256>>>(att_src1, att_dst1);
    edge_max1_kernel<<<(ET + 255) / 256, 256>>>(ei);
    edge_sum1_kernel<<<(ET * 32 + 255) / 256, 256>>>(ei);
    finalize1_kernel<<<4096, 256>>>(b1);

    // layer 2
    {
        dim3 grid((OUT_CH + 63) / 64, (N_NODES + 63) / 64);
        sgemm_kernel<<<grid, 256>>>(h, W2, xp2, N_NODES, C1, OUT_CH);
    }
    attn2_kernel<<<(N_NODES * 32 + 255) / 256, 256>>>(att_src2, att_dst2);
    edge_max2_kernel<<<(ET + 255) / 256, 256>>>(ei);
    edge_sum2_kernel<<<(ET * 32 + 255) / 256, 256>>>(ei);
    final_kernel<<<(N_NODES * 32 + 255) / 256, 256>>>(b2, out);
}

// round 4
// speedup vs baseline: 1.0268x; 1.0268x over previous
#include <cuda_runtime.h>
#include <math.h>

#define N_NODES 100000
#define E_EDGES 800000
#define ET (E_EDGES + N_NODES)   // edges + self loops = 900000
#define IN_CH 128
#define HID 32
#define HEADS 8
#define C1 (HEADS * HID)          // 256
#define OUT_CH 40
#define NEG_SLOPE 0.2f

// ---------------- scratch (device globals; no allocation allowed) ----------
__device__ float g_xp1[N_NODES * C1];
__device__ float g_acc1[N_NODES * C1];
__device__ float g_h[N_NODES * C1];
__device__ float g_xp2[N_NODES * OUT_CH];
__device__ float g_acc2[N_NODES * OUT_CH];
__device__ float g_as1[N_NODES * HEADS];
__device__ float g_ad1[N_NODES * HEADS];
__device__ float g_m1[N_NODES * HEADS];
__device__ float g_z1[N_NODES * HEADS];
__device__ float g_as2[N_NODES];
__device__ float g_ad2[N_NODES];
__device__ float g_m2[N_NODES];
__device__ float g_z2[N_NODES];

__device__ __forceinline__ void atomicMaxF(float* addr, float val) {
    if (val >= 0.0f) atomicMax((int*)addr, __float_as_int(val));
    else             atomicMin((unsigned int*)addr, (unsigned int)__float_as_int(val));
}

__device__ __forceinline__ float leaky(float x) {
    return x > 0.0f ? x : NEG_SLOPE * x;
}

// ---------------- init ------------------------------------------------------
__global__ void init_kernel() {
    int stride = gridDim.x * blockDim.x;
    for (int i = blockIdx.x * blockDim.x + threadIdx.x; i < N_NODES * C1; i += stride) {
        g_acc1[i] = 0.0f;
        if (i < N_NODES * OUT_CH) g_acc2[i] = 0.0f;
        if (i < N_NODES * HEADS) { g_m1[i] = -INFINITY; g_z1[i] = 0.0f; }
        if (i < N_NODES)         { g_m2[i] = -INFINITY; g_z2[i] = 0.0f; }
    }
}

// ============ GEMM1: C[M,256] = A[M,128] @ B[128,256] =======================
// BM=128, BN=128, BK=8, 256 threads, 8x8/thread, double-buffered smem.
__global__ __launch_bounds__(256) void sgemm1_kernel(const float* __restrict__ A,
                                                     const float* __restrict__ B,
                                                     float* __restrict__ C, int M) {
    __shared__ float As[2][8][128];
    __shared__ float Bs[2][8][128];

    const int tid = threadIdx.x;
    const int rowBase = blockIdx.y * 128;
    const int colBase = blockIdx.x * 128;

    // gmem load mapping
    const int arow = tid >> 1;          // 0..127
    const int akq  = (tid & 1) * 4;     // 0 or 4
    const int bkr  = tid >> 5;          // 0..7
    const int bcol = (tid & 31) * 4;    // 0..124

    // compute mapping
    const int ty = tid >> 4;            // 0..15
    const int tx = tid & 15;            // 0..15

    float acc[8][8];
#pragma unroll
    for (int i = 0; i < 8; i++)
#pragma unroll
        for (int j = 0; j < 8; j++) acc[i][j] = 0.0f;

    const int gr = rowBase + arow;
    float4 av, bv;

    // prologue: stage 0 -> buffer 0
    av = make_float4(0.f, 0.f, 0.f, 0.f);
    if (gr < M) av = *(const float4*)&A[(long)gr * IN_CH + akq];
    bv = *(const float4*)&B[(long)bkr * C1 + colBase + bcol];
    As[0][akq + 0][arow] = av.x;
    As[0][akq + 1][arow] = av.y;
    As[0][akq + 2][arow] = av.z;
    As[0][akq + 3][arow] = av.w;
    *(float4*)&Bs[0][bkr][bcol] = bv;
    __syncthreads();

    int p = 0;
#pragma unroll
    for (int s = 0; s < 16; s++) {
        if (s < 15) {
            int k0 = (s + 1) * 8;
            av = make_float4(0.f, 0.f, 0.f, 0.f);
            if (gr < M) av = *(const float4*)&A[(long)gr * IN_CH + k0 + akq];
            bv = *(const float4*)&B[(long)(k0 + bkr) * C1 + colBase + bcol];
        }
#pragma unroll
        for (int k = 0; k < 8; k++) {
            float a[8], b[8];
            *(float4*)&a[0] = *(const float4*)&As[p][k][ty * 4];
            *(float4*)&a[4] = *(const float4*)&As[p][k][64 + ty * 4];
            *(float4*)&b[0] = *(const float4*)&Bs[p][k][tx * 4];
            *(float4*)&b[4] = *(const float4*)&Bs[p][k][64 + tx * 4];
#pragma unroll
            for (int i = 0; i < 8; i++)
#pragma unroll
                for (int j = 0; j < 8; j++) acc[i][j] += a[i] * b[j];
        }
        if (s < 15) {
            p ^= 1;
            As[p][akq + 0][arow] = av.x;
            As[p][akq + 1][arow] = av.y;
            As[p][akq + 2][arow] = av.z;
            As[p][akq + 3][arow] = av.w;
            *(float4*)&Bs[p][bkr][bcol] = bv;
            __syncthreads();
        }
    }

    // epilogue
#pragma unroll
    for (int ii = 0; ii < 2; ii++) {
#pragma unroll
        for (int i = 0; i < 4; i++) {
            int r = rowBase + ii * 64 + ty * 4 + i;
            if (r >= M) continue;
            float4 v0 = make_float4(acc[ii*4+i][0], acc[ii*4+i][1], acc[ii*4+i][2], acc[ii*4+i][3]);
            float4 v1 = make_float4(acc[ii*4+i][4], acc[ii*4+i][5], acc[ii*4+i][6], acc[ii*4+i][7]);
            *(float4*)&C[(long)r * C1 + colBase + tx * 4]      = v0;
            *(float4*)&C[(long)r * C1 + colBase + 64 + tx * 4] = v1;
        }
    }
}

// ============ GEMM2: C[M,40] = A[M,256] @ B[256,40] =========================
// BM=128, BN=40 (exact), BK=16, 256 threads, 4x5/thread, double-buffered.
__global__ __launch_bounds__(256) void sgemm2_kernel(const float* __restrict__ A,
                                                     const float* __restrict__ B,
                                                     float* __restrict__ C, int M) {
    __shared__ float As[2][16][128];
    __shared__ float Bs[2][16][40];

    const int tid = threadIdx.x;
    const int rowBase = blockIdx.x * 128;

    const int arow = tid >> 1;          // 0..127
    const int akq  = (tid & 1) * 8;     // 0 or 8

    const int ty = tid >> 3;            // 0..31 -> 4 rows each
    const int tx = tid & 7;             // 0..7  -> 5 cols each

    float acc[4][5];
#pragma unroll
    for (int i = 0; i < 4; i++)
#pragma unroll
        for (int j = 0; j < 5; j++) acc[i][j] = 0.0f;

    const int gr = rowBase + arow;
    float4 av0, av1;
    float bsc[3];

    // prologue
    av0 = make_float4(0.f, 0.f, 0.f, 0.f);
    av1 = make_float4(0.f, 0.f, 0.f, 0.f);
    if (gr < M) {
        av0 = *(const float4*)&A[(long)gr * C1 + akq];
        av1 = *(const float4*)&A[(long)gr * C1 + akq + 4];
    }
#pragma unroll
    for (int t = 0; t < 3; t++) {
        int idx = tid + t * 256;
        bsc[t] = (idx < 16 * 40) ? B[(long)(idx / 40) * OUT_CH + idx % 40] : 0.f;
    }
    {
        As[0][akq + 0][arow] = av0.x; As[0][akq + 1][arow] = av0.y;
        As[0][akq + 2][arow] = av0.z; As[0][akq + 3][arow] = av0.w;
        As[0][akq + 4][arow] = av1.x; As[0][akq + 5][arow] = av1.y;
        As[0][akq + 6][arow] = av1.z; As[0][akq + 7][arow] = av1.w;
#pragma unroll
        for (int t = 0; t < 3; t++) {
            int idx = tid + t * 256;
            if (idx < 16 * 40) Bs[0][idx / 40][idx % 40] = bsc[t];
        }
    }
    __syncthreads();

    int p = 0;
#pragma unroll
    for (int s = 0; s < 16; s++) {
        if (s < 15) {
            int k0 = (s + 1) * 16;
            av0 = make_float4(0.f, 0.f, 0.f, 0.f);
            av1 = make_float4(0.f, 0.f, 0.f, 0.f);
            if (gr < M) {
                av0 = *(const float4*)&A[(long)gr * C1 + k0 + akq];
                av1 = *(const float4*)&A[(long)gr * C1 + k0 + akq + 4];
            }
#pragma unroll
            for (int t = 0; t < 3; t++) {
                int idx = tid + t * 256;
                bsc[t] = (idx < 16 * 40) ? B[(long)(k0 + idx / 40) * OUT_CH + idx % 40] : 0.f;
            }
        }
#pragma unroll
        for (int k = 0; k < 16; k++) {
            float a[4], b[5];
            *(float4*)&a[0] = *(const float4*)&As[p][k][ty * 4];
#pragma unroll
            for (int j = 0; j < 5; j++) b[j] = Bs[p][k][tx * 5 + j];
#pragma unroll
            for (int i = 0; i < 4; i++)
#pragma unroll
                for (int j = 0; j < 5; j++) acc[i][j] += a[i] * b[j];
        }
        if (s < 15) {
            p ^= 1;
            As[p][akq + 0][arow] = av0.x; As[p][akq + 1][arow] = av0.y;
            As[p][akq + 2][arow] = av0.z; As[p][akq + 3][arow] = av0.w;
            As[p][akq + 4][arow] = av1.x; As[p][akq + 5][arow] = av1.y;
            As[p][akq + 6][arow] = av1.z; As[p][akq + 7][arow] = av1.w;
#pragma unroll
            for (int t = 0; t < 3; t++) {
                int idx = tid + t * 256;
                if (idx < 16 * 40) Bs[p][idx / 40][idx % 40] = bsc[t];
            }
            __syncthreads();
        }
    }

#pragma unroll
    for (int i = 0; i < 4; i++) {
        int r = rowBase + ty * 4 + i;
        if (r >= M) continue;
#pragma unroll
        for (int j = 0; j < 5; j++) C[(long)r * OUT_CH + tx * 5 + j] = acc[i][j];
    }
}

// ---------------- attention coefficients, layer 1 (warp per node) -----------
__global__ void attn1_kernel(const float* __restrict__ att_src,
                             const float* __restrict__ att_dst) {
    int warp = (blockIdx.x * blockDim.x + threadIdx.x) >> 5;
    int lane = threadIdx.x & 31;
    if (warp >= N_NODES) return;
    const float* xp = &g_xp1[(long)warp * C1];
#pragma unroll
    for (int it = 0; it < 8; it++) {
        int c = it * 32 + lane;
        float v = xp[c];
        float ps = v * att_src[c];
        float pd = v * att_dst[c];
#pragma unroll
        for (int o = 16; o > 0; o >>= 1) {
            ps += __shfl_xor_sync(0xffffffffu, ps, o);
            pd += __shfl_xor_sync(0xffffffffu, pd, o);
        }
        if (lane == 0) {
            g_as1[warp * 8 + it] = ps;
            g_ad1[warp * 8 + it] = pd;
        }
    }
}

// ---------------- edge pass 1a: segment max (thread per edge) ---------------
__global__ void edge_max1_kernel(const int* __restrict__ ei) {
    int e = blockIdx.x * blockDim.x + threadIdx.x;
    if (e >= ET) return;
    int src, dst;
    if (e < E_EDGES) { src = ei[e]; dst = ei[E_EDGES + e]; }
    else             { src = dst = e - E_EDGES; }
    const float4 s0 = *(const float4*)&g_as1[src * 8];
    const float4 s1 = *(const float4*)&g_as1[src * 8 + 4];
    const float4 d0 = *(const float4*)&g_ad1[dst * 8];
    const float4 d1 = *(const float4*)&g_ad1[dst * 8 + 4];
    float ls[8] = {s0.x + d0.x, s0.y + d0.y, s0.z + d0.z, s0.w + d0.w,
                   s1.x + d1.x, s1.y + d1.y, s1.z + d1.z, s1.w + d1.w};
#pragma unroll
    for (int h = 0; h < 8; h++) atomicMaxF(&g_m1[dst * 8 + h], leaky(ls[h]));
}

// ---------------- edge pass 1b: exp + weighted aggregate (warp per edge) ----
__global__ void edge_sum1_kernel(const int* __restrict__ ei) {
    int warp = (blockIdx.x * blockDim.x + threadIdx.x) >> 5;
    int lane = threadIdx.x & 31;
    if (warp >= ET) return;
    int src, dst;
    if (warp < E_EDGES) { src = ei[warp]; dst = ei[E_EDGES + warp]; }
    else                { src = dst = warp - E_EDGES; }
    float p = 0.0f;
    if (lane < 8) {
        float l = leaky(g_as1[src * 8 + lane] + g_ad1[dst * 8 + lane]);
        p = __expf(l - g_m1[dst * 8 + lane]);
        atomicAdd(&g_z1[dst * 8 + lane], p);
    }
    const float* xs = &g_xp1[(long)src * C1];
    float* ad = &g_acc1[(long)dst * C1];
#pragma unroll
    for (int h = 0; h < 8; h++) {
        float ph = __shfl_sync(0xffffffffu, p, h);
        atomicAdd(&ad[h * 32 + lane], ph * xs[h * 32 + lane]);
    }
}

// ---------------- finalize layer 1: divide, bias, relu ----------------------
__global__ void finalize1_kernel(const float* __restrict__ b1) {
    int stride = gridDim.x * blockDim.x;
    for (int i = blockIdx.x * blockDim.x + threadIdx.x; i < N_NODES * C1; i += stride) {
        int n = i >> 8;
        int c = i & 255;
        float z = g_z1[n * 8 + (c >> 5)] + 1e-16f;
        float v = g_acc1[i] / z + b1[c];
        g_h[i] = v > 0.0f ? v : 0.0f;
    }
}

// ---------------- attention coefficients, layer 2 (warp per node) -----------
__global__ void attn2_kernel(const float* __restrict__ att_src,
                             const float* __restrict__ att_dst) {
    int warp = (blockIdx.x * blockDim.x + threadIdx.x) >> 5;
    int lane = threadIdx.x & 31;
    if (warp >= N_NODES) return;
    const float* xp = &g_xp2[(long)warp * OUT_CH];
    float v = xp[lane];
    float s = v * att_src[lane];
    float d = v * att_dst[lane];
    if (lane < 8) {
        float v2 = xp[32 + lane];
        s += v2 * att_src[32 + lane];
        d += v2 * att_dst[32 + lane];
    }
#pragma unroll
    for (int o = 16; o > 0; o >>= 1) {
        s += __shfl_xor_sync(0xffffffffu, s, o);
        d += __shfl_xor_sync(0xffffffffu, d, o);
    }
    if (lane == 0) { g_as2[warp] = s; g_ad2[warp] = d; }
}

__global__ void edge_max2_kernel(const int* __restrict__ ei) {
    int e = blockIdx.x * blockDim.x + threadIdx.x;
    if (e >= ET) return;
    int src, dst;
    if (e < E_EDGES) { src = ei[e]; dst = ei[E_EDGES + e]; }
    else             { src = dst = e - E_EDGES; }
    atomicMaxF(&g_m2[dst], leaky(g_as2[src] + g_ad2[dst]));
}

__global__ void edge_sum2_kernel(const int* __restrict__ ei) {
    int warp = (blockIdx.x * blockDim.x + threadIdx.x) >> 5;
    int lane = threadIdx.x & 31;
    if (warp >= ET) return;
    int src, dst;
    if (warp < E_EDGES) { src = ei[warp]; dst = ei[E_EDGES + warp]; }
    else                { src = dst = warp - E_EDGES; }
    float p = __expf(leaky(g_as2[src] + g_ad2[dst]) - g_m2[dst]);
    if (lane == 0) atomicAdd(&g_z2[dst], p);
    const float* xs = &g_xp2[(long)src * OUT_CH];
    float* ad = &g_acc2[(long)dst * OUT_CH];
    atomicAdd(&ad[lane], p * xs[lane]);
    if (lane < 8) atomicAdd(&ad[32 + lane], p * xs[32 + lane]);
}

// ---------------- finalize layer 2 + log_softmax (warp per node) ------------
__global__ void final_kernel(const float* __restrict__ b2, float* __restrict__ out) {
    int warp = (blockIdx.x * blockDim.x + threadIdx.x) >> 5;
    int lane = threadIdx.x & 31;
    if (warp >= N_NODES) return;
    float z = g_z2[warp] + 1e-16f;
    const float* ac = &g_acc2[(long)warp * OUT_CH];
    float x1 = ac[lane] / z + b2[lane];
    float x2 = (lane < 8) ? (ac[32 + lane] / z + b2[32 + lane]) : -INFINITY;
    float mx = fmaxf(x1, x2);
#pragma unroll
    for (int o = 16; o > 0; o >>= 1) mx = fmaxf(mx, __shfl_xor_sync(0xffffffffu, mx, o));
    float se = __expf(x1 - mx) + ((lane < 8) ? __expf(x2 - mx) : 0.0f);
#pragma unroll
    for (int o = 16; o > 0; o >>= 1) se += __shfl_xor_sync(0xffffffffu, se, o);
    float lse = mx + logf(se);
    out[(long)warp * OUT_CH + lane] = x1 - lse;
    if (lane < 8) out[(long)warp * OUT_CH + 32 + lane] = x2 - lse;
}

// ---------------- launch ----------------------------------------------------
extern "C" void kernel_launch(void* const* d_in, const int* in_sizes, int n_in,
                              void* d_out, int out_size) {
    const float* x        = (const float*)d_in[0];
    const int*   ei       = (const int*)d_in[1];     // int32: JAX demotes int64
    const float* W1       = (const float*)d_in[2];
    const float* att_src1 = (const float*)d_in[3];
    const float* att_dst1 = (const float*)d_in[4];
    const float* b1       = (const float*)d_in[5];
    const float* W2       = (const float*)d_in[6];
    const float* att_src2 = (const float*)d_in[7];
    const float* att_dst2 = (const float*)d_in[8];
    const float* b2       = (const float*)d_in[9];
    float*       out      = (float*)d_out;

    float* xp1 = nullptr; float* h = nullptr; float* xp2 = nullptr;
    cudaGetSymbolAddress((void**)&xp1, g_xp1);
    cudaGetSymbolAddress((void**)&h,   g_h);
    cudaGetSymbolAddress((void**)&xp2, g_xp2);

    init_kernel<<<4096, 256>>>();

    // layer 1
    {
        dim3 grid(C1 / 128, (N_NODES + 127) / 128);
        sgemm1_kernel<<<grid, 256>>>(x, W1, xp1, N_NODES);
    }
    attn1_kernel<<<(N_NODES * 32 + 255) / 256, 256>>>(att_src1, att_dst1);
    edge_max1_kernel<<<(ET + 255) / 256, 256>>>(ei);
    edge_sum1_kernel<<<(ET * 32 + 255) / 256, 256>>>(ei);
    finalize1_kernel<<<4096, 256>>>(b1);

    // layer 2
    sgemm2_kernel<<<(N_NODES + 127) / 128, 256>>>(h, W2, xp2, N_NODES);
    attn2_kernel<<<(N_NODES * 32 + 255) / 256, 256>>>(att_src2, att_dst2);
    edge_max2_kernel<<<(ET + 255) / 256, 256>>>(ei);
    edge_sum2_kernel<<<(ET * 32 + 255) / 256, 256>>>(ei);
    final_kernel<<<(N_NODES * 32 + 255) / 256, 256>>>(b2, out);
}

// round 5
// speedup vs baseline: 1.5277x; 1.4878x over previous
#include <cuda_runtime.h>
#include <math.h>

#define N_NODES 100000
#define E_EDGES 800000
#define ET (E_EDGES + N_NODES)   // edges + self loops = 900000
#define IN_CH 128
#define HID 32
#define HEADS 8
#define C1 (HEADS * HID)          // 256
#define OUT_CH 40
#define NEG_SLOPE 0.2f

// ---------------- scratch (device globals; no allocation allowed) ----------
__device__ float g_xp1[N_NODES * C1];
__device__ float g_h[N_NODES * C1];
__device__ float g_xp2[N_NODES * OUT_CH];
__device__ float g_as1[N_NODES * HEADS];
__device__ float g_ad1[N_NODES * HEADS];
__device__ float g_as2[N_NODES];
__device__ float g_ad2[N_NODES];

__device__ int g_deg[N_NODES];
__device__ int g_rowstart[N_NODES + 1];
__device__ int g_cursor[N_NODES];
__device__ int g_csrc[ET];

__device__ __forceinline__ float leaky(float x) {
    return x > 0.0f ? x : NEG_SLOPE * x;
}

// ================= CSR build =================================================
__global__ void zero_deg_kernel() {
    int i = blockIdx.x * blockDim.x + threadIdx.x;
    if (i < N_NODES) g_deg[i] = 0;
}

__global__ void hist_kernel(const int* __restrict__ ei) {
    int e = blockIdx.x * blockDim.x + threadIdx.x;
    if (e >= ET) return;
    int dst = (e < E_EDGES) ? ei[E_EDGES + e] : e - E_EDGES;
    atomicAdd(&g_deg[dst], 1);
}

// single block, 1024 threads: exclusive scan of g_deg -> g_rowstart, g_cursor
__global__ void scan_kernel() {
    __shared__ int sums[1024];
    const int t = threadIdx.x;
    const int CH = (N_NODES + 1023) / 1024;   // 98
    int lo = t * CH;
    int hi = lo + CH; if (hi > N_NODES) hi = N_NODES;
    int s = 0;
    for (int i = lo; i < hi; i++) s += g_deg[i];
    sums[t] = s;
    __syncthreads();
    for (int o = 1; o < 1024; o <<= 1) {
        int u = (t >= o) ? sums[t - o] : 0;
        __syncthreads();
        sums[t] += u;
        __syncthreads();
    }
    int run = sums[t] - s;   // exclusive prefix for this chunk
    for (int i = lo; i < hi; i++) {
        g_rowstart[i] = run;
        g_cursor[i]   = run;
        run += g_deg[i];
    }
    if (t == 0) g_rowstart[N_NODES] = ET;
}

__global__ void scatter_kernel(const int* __restrict__ ei) {
    int e = blockIdx.x * blockDim.x + threadIdx.x;
    if (e >= ET) return;
    int src, dst;
    if (e < E_EDGES) { src = ei[e]; dst = ei[E_EDGES + e]; }
    else             { src = dst = e - E_EDGES; }
    int pos = atomicAdd(&g_cursor[dst], 1);
    g_csrc[pos] = src;
}

// ============ GEMM1: C[M,256] = A[M,128] @ B[128,256] =======================
// BM=128, BN=128, BK=8, 256 threads, 8x8/thread, double-buffered smem.
__global__ __launch_bounds__(256) void sgemm1_kernel(const float* __restrict__ A,
                                                     const float* __restrict__ B,
                                                     float* __restrict__ C, int M) {
    __shared__ float As[2][8][128];
    __shared__ float Bs[2][8][128];

    const int tid = threadIdx.x;
    const int rowBase = blockIdx.y * 128;
    const int colBase = blockIdx.x * 128;

    const int arow = tid >> 1;
    const int akq  = (tid & 1) * 4;
    const int bkr  = tid >> 5;
    const int bcol = (tid & 31) * 4;

    const int ty = tid >> 4;
    const int tx = tid & 15;

    float acc[8][8];
#pragma unroll
    for (int i = 0; i < 8; i++)
#pragma unroll
        for (int j = 0; j < 8; j++) acc[i][j] = 0.0f;

    const int gr = rowBase + arow;
    float4 av, bv;

    av = make_float4(0.f, 0.f, 0.f, 0.f);
    if (gr < M) av = *(const float4*)&A[(long)gr * IN_CH + akq];
    bv = *(const float4*)&B[(long)bkr * C1 + colBase + bcol];
    As[0][akq + 0][arow] = av.x;
    As[0][akq + 1][arow] = av.y;
    As[0][akq + 2][arow] = av.z;
    As[0][akq + 3][arow] = av.w;
    *(float4*)&Bs[0][bkr][bcol] = bv;
    __syncthreads();

    int p = 0;
#pragma unroll
    for (int s = 0; s < 16; s++) {
        if (s < 15) {
            int k0 = (s + 1) * 8;
            av = make_float4(0.f, 0.f, 0.f, 0.f);
            if (gr < M) av = *(const float4*)&A[(long)gr * IN_CH + k0 + akq];
            bv = *(const float4*)&B[(long)(k0 + bkr) * C1 + colBase + bcol];
        }
#pragma unroll
        for (int k = 0; k < 8; k++) {
            float a[8], b[8];
            *(float4*)&a[0] = *(const float4*)&As[p][k][ty * 4];
            *(float4*)&a[4] = *(const float4*)&As[p][k][64 + ty * 4];
            *(float4*)&b[0] = *(const float4*)&Bs[p][k][tx * 4];
            *(float4*)&b[4] = *(const float4*)&Bs[p][k][64 + tx * 4];
#pragma unroll
            for (int i = 0; i < 8; i++)
#pragma unroll
                for (int j = 0; j < 8; j++) acc[i][j] += a[i] * b[j];
        }
        if (s < 15) {
            p ^= 1;
            As[p][akq + 0][arow] = av.x;
            As[p][akq + 1][arow] = av.y;
            As[p][akq + 2][arow] = av.z;
            As[p][akq + 3][arow] = av.w;
            *(float4*)&Bs[p][bkr][bcol] = bv;
            __syncthreads();
        }
    }

#pragma unroll
    for (int ii = 0; ii < 2; ii++) {
#pragma unroll
        for (int i = 0; i < 4; i++) {
            int r = rowBase + ii * 64 + ty * 4 + i;
            if (r >= M) continue;
            float4 v0 = make_float4(acc[ii*4+i][0], acc[ii*4+i][1], acc[ii*4+i][2], acc[ii*4+i][3]);
            float4 v1 = make_float4(acc[ii*4+i][4], acc[ii*4+i][5], acc[ii*4+i][6], acc[ii*4+i][7]);
            *(float4*)&C[(long)r * C1 + colBase + tx * 4]      = v0;
            *(float4*)&C[(long)r * C1 + colBase + 64 + tx * 4] = v1;
        }
    }
}

// ============ GEMM2: C[M,40] = A[M,256] @ B[256,40] =========================
__global__ __launch_bounds__(256) void sgemm2_kernel(const float* __restrict__ A,
                                                     const float* __restrict__ B,
                                                     float* __restrict__ C, int M) {
    __shared__ float As[2][16][128];
    __shared__ float Bs[2][16][40];

    const int tid = threadIdx.x;
    const int rowBase = blockIdx.x * 128;

    const int arow = tid >> 1;
    const int akq  = (tid & 1) * 8;

    const int ty = tid >> 3;
    const int tx = tid & 7;

    float acc[4][5];
#pragma unroll
    for (int i = 0; i < 4; i++)
#pragma unroll
        for (int j = 0; j < 5; j++) acc[i][j] = 0.0f;

    const int gr = rowBase + arow;
    float4 av0, av1;
    float bsc[3];

    av0 = make_float4(0.f, 0.f, 0.f, 0.f);
    av1 = make_float4(0.f, 0.f, 0.f, 0.f);
    if (gr < M) {
        av0 = *(const float4*)&A[(long)gr * C1 + akq];
        av1 = *(const float4*)&A[(long)gr * C1 + akq + 4];
    }
#pragma unroll
    for (int t = 0; t < 3; t++) {
        int idx = tid + t * 256;
        bsc[t] = (idx < 16 * 40) ? B[(long)(idx / 40) * OUT_CH + idx % 40] : 0.f;
    }
    As[0][akq + 0][arow] = av0.x; As[0][akq + 1][arow] = av0.y;
    As[0][akq + 2][arow] = av0.z; As[0][akq + 3][arow] = av0.w;
    As[0][akq + 4][arow] = av1.x; As[0][akq + 5][arow] = av1.y;
    As[0][akq + 6][arow] = av1.z; As[0][akq + 7][arow] = av1.w;
#pragma unroll
    for (int t = 0; t < 3; t++) {
        int idx = tid + t * 256;
        if (idx < 16 * 40) Bs[0][idx / 40][idx % 40] = bsc[t];
    }
    __syncthreads();

    int p = 0;
#pragma unroll
    for (int s = 0; s < 16; s++) {
        if (s < 15) {
            int k0 = (s + 1) * 16;
            av0 = make_float4(0.f, 0.f, 0.f, 0.f);
            av1 = make_float4(0.f, 0.f, 0.f, 0.f);
            if (gr < M) {
                av0 = *(const float4*)&A[(long)gr * C1 + k0 + akq];
                av1 = *(const float4*)&A[(long)gr * C1 + k0 + akq + 4];
            }
#pragma unroll
            for (int t = 0; t < 3; t++) {
                int idx = tid + t * 256;
                bsc[t] = (idx < 16 * 40) ? B[(long)(k0 + idx / 40) * OUT_CH + idx % 40] : 0.f;
            }
        }
#pragma unroll
        for (int k = 0; k < 16; k++) {
            float a[4], b[5];
            *(float4*)&a[0] = *(const float4*)&As[p][k][ty * 4];
#pragma unroll
            for (int j = 0; j < 5; j++) b[j] = Bs[p][k][tx * 5 + j];
#pragma unroll
            for (int i = 0; i < 4; i++)
#pragma unroll
                for (int j = 0; j < 5; j++) acc[i][j] += a[i] * b[j];
        }
        if (s < 15) {
            p ^= 1;
            As[p][akq + 0][arow] = av0.x; As[p][akq + 1][arow] = av0.y;
            As[p][akq + 2][arow] = av0.z; As[p][akq + 3][arow] = av0.w;
            As[p][akq + 4][arow] = av1.x; As[p][akq + 5][arow] = av1.y;
            As[p][akq + 6][arow] = av1.z; As[p][akq + 7][arow] = av1.w;
#pragma unroll
            for (int t = 0; t < 3; t++) {
                int idx = tid + t * 256;
                if (idx < 16 * 40) Bs[p][idx / 40][idx % 40] = bsc[t];
            }
            __syncthreads();
        }
    }

#pragma unroll
    for (int i = 0; i < 4; i++) {
        int r = rowBase + ty * 4 + i;
        if (r >= M) continue;
#pragma unroll
        for (int j = 0; j < 5; j++) C[(long)r * OUT_CH + tx * 5 + j] = acc[i][j];
    }
}

// ---------------- attention coefficients, layer 1 (warp per node) -----------
__global__ void attn1_kernel(const float* __restrict__ att_src,
                             const float* __restrict__ att_dst) {
    int warp = (blockIdx.x * blockDim.x + threadIdx.x) >> 5;
    int lane = threadIdx.x & 31;
    if (warp >= N_NODES) return;
    const float* xp = &g_xp1[(long)warp * C1];
#pragma unroll
    for (int it = 0; it < 8; it++) {
        int c = it * 32 + lane;
        float v = xp[c];
        float ps = v * att_src[c];
        float pd = v * att_dst[c];
#pragma unroll
        for (int o = 16; o > 0; o >>= 1) {
            ps += __shfl_xor_sync(0xffffffffu, ps, o);
            pd += __shfl_xor_sync(0xffffffffu, pd, o);
        }
        if (lane == 0) {
            g_as1[warp * 8 + it] = ps;
            g_ad1[warp * 8 + it] = pd;
        }
    }
}

// ---------------- layer-1 aggregation: warp per dst node, no atomics --------
__global__ __launch_bounds__(256) void agg1_kernel(const float* __restrict__ b1) {
    int n = (blockIdx.x * blockDim.x + threadIdx.x) >> 5;
    int lane = threadIdx.x & 31;
    if (n >= N_NODES) return;
    const int start = g_rowstart[n];
    const int end   = g_rowstart[n + 1];

    const int h   = lane & 7;       // head handled by this lane
    const int grp = lane >> 3;      // 4 parallel edge groups for max pass
    const float adv = g_ad1[n * 8 + h];

    // pass 1: per-head max
    float m = -INFINITY;
    for (int i = start + grp; i < end; i += 4) {
        int s = g_csrc[i];
        m = fmaxf(m, leaky(g_as1[s * 8 + h] + adv));
    }
    m = fmaxf(m, __shfl_xor_sync(0xffffffffu, m, 8));
    m = fmaxf(m, __shfl_xor_sync(0xffffffffu, m, 16));
    // now lanes 0..7 hold max for head=lane

    // pass 2: exp + weighted accumulate (serial over incident edges)
    float acc[8] = {0.f, 0.f, 0.f, 0.f, 0.f, 0.f, 0.f, 0.f};
    float z = 0.f;
    for (int i = start; i < end; i++) {
        int s = g_csrc[i];
        float p = 0.f;
        if (lane < 8) {
            p = __expf(leaky(g_as1[s * 8 + lane] + adv) - m);
            z += p;
        }
        const float* xs = &g_xp1[(long)s * C1];
#pragma unroll
        for (int hh = 0; hh < 8; hh++) {
            float ph = __shfl_sync(0xffffffffu, p, hh);
            acc[hh] += ph * xs[hh * 32 + lane];
        }
    }

    // finalize: divide, bias, relu -> g_h
    float* hd = &g_h[(long)n * C1];
#pragma unroll
    for (int hh = 0; hh < 8; hh++) {
        float zh = __shfl_sync(0xffffffffu, z, hh);
        float v = acc[hh] / (zh + 1e-16f) + b1[hh * 32 + lane];
        hd[hh * 32 + lane] = fmaxf(v, 0.f);
    }
}

// ---------------- attention coefficients, layer 2 (warp per node) -----------
__global__ void attn2_kernel(const float* __restrict__ att_src,
                             const float* __restrict__ att_dst) {
    int warp = (blockIdx.x * blockDim.x + threadIdx.x) >> 5;
    int lane = threadIdx.x & 31;
    if (warp >= N_NODES) return;
    const float* xp = &g_xp2[(long)warp * OUT_CH];
    float v = xp[lane];
    float s = v * att_src[lane];
    float d = v * att_dst[lane];
    if (lane < 8) {
        float v2 = xp[32 + lane];
        s += v2 * att_src[32 + lane];
        d += v2 * att_dst[32 + lane];
    }
#pragma unroll
    for (int o = 16; o > 0; o >>= 1) {
        s += __shfl_xor_sync(0xffffffffu, s, o);
        d += __shfl_xor_sync(0xffffffffu, d, o);
    }
    if (lane == 0) { g_as2[warp] = s; g_ad2[warp] = d; }
}

// ---------- layer-2 aggregation + log_softmax: warp per dst node ------------
__global__ __launch_bounds__(256) void agg2_kernel(const float* __restrict__ b2,
                                                   float* __restrict__ out) {
    int n = (blockIdx.x * blockDim.x + threadIdx.x) >> 5;
    int lane = threadIdx.x & 31;
    if (n >= N_NODES) return;
    const int start = g_rowstart[n];
    const int end   = g_rowstart[n + 1];
    const float adn = g_ad2[n];

    // pass 1: max over incident edges
    float m = -INFINITY;
    for (int i = start + lane; i < end; i += 32)
        m = fmaxf(m, leaky(g_as2[g_csrc[i]] + adn));
#pragma unroll
    for (int o = 16; o > 0; o >>= 1)
        m = fmaxf(m, __shfl_xor_sync(0xffffffffu, m, o));

    // pass 2: exp + weighted accumulate
    float a0 = 0.f, a1 = 0.f, z = 0.f;
    for (int i = start; i < end; i++) {
        int s = g_csrc[i];
        float p = __expf(leaky(g_as2[s] + adn) - m);   // same on all lanes
        z += p;
        const float* xs = &g_xp2[(long)s * OUT_CH];
        a0 += p * xs[lane];
        if (lane < 8) a1 += p * xs[32 + lane];
    }
    float zi = 1.0f / (z + 1e-16f);

    // log_softmax over 40 channels
    float x1 = a0 * zi + b2[lane];
    float x2 = (lane < 8) ? (a1 * zi + b2[32 + lane]) : -INFINITY;
    float mx = fmaxf(x1, x2);
#pragma unroll
    for (int o = 16; o > 0; o >>= 1) mx = fmaxf(mx, __shfl_xor_sync(0xffffffffu, mx, o));
    float se = __expf(x1 - mx) + ((lane < 8) ? __expf(x2 - mx) : 0.0f);
#pragma unroll
    for (int o = 16; o > 0; o >>= 1) se += __shfl_xor_sync(0xffffffffu, se, o);
    float lse = mx + logf(se);
    out[(long)n * OUT_CH + lane] = x1 - lse;
    if (lane < 8) out[(long)n * OUT_CH + 32 + lane] = x2 - lse;
}

// ---------------- launch ----------------------------------------------------
extern "C" void kernel_launch(void* const* d_in, const int* in_sizes, int n_in,
                              void* d_out, int out_size) {
    const float* x        = (const float*)d_in[0];
    const int*   ei       = (const int*)d_in[1];     // int32: JAX demotes int64
    const float* W1       = (const float*)d_in[2];
    const float* att_src1 = (const float*)d_in[3];
    const float* att_dst1 = (const float*)d_in[4];
    const float* b1       = (const float*)d_in[5];
    const float* W2       = (const float*)d_in[6];
    const float* att_src2 = (const float*)d_in[7];
    const float* att_dst2 = (const float*)d_in[8];
    const float* b2       = (const float*)d_in[9];
    float*       out      = (float*)d_out;

    float* xp1 = nullptr; float* h = nullptr; float* xp2 = nullptr;
    cudaGetSymbolAddress((void**)&xp1, g_xp1);
    cudaGetSymbolAddress((void**)&h,   g_h);
    cudaGetSymbolAddress((void**)&xp2, g_xp2);

    // CSR build (shared by both layers)
    zero_deg_kernel<<<(N_NODES + 255) / 256, 256>>>();
    hist_kernel<<<(ET + 255) / 256, 256>>>(ei);
    scan_kernel<<<1, 1024>>>();
    scatter_kernel<<<(ET + 255) / 256, 256>>>(ei);

    // layer 1
    {
        dim3 grid(C1 / 128, (N_NODES + 127) / 128);
        sgemm1_kernel<<<grid, 256>>>(x, W1, xp1, N_NODES);
    }
    attn1_kernel<<<(N_NODES * 32 + 255) / 256, 256>>>(att_src1, att_dst1);
    agg1_kernel<<<(N_NODES * 32 + 255) / 256, 256>>>(b1);

    // layer 2
    sgemm2_kernel<<<(N_NODES + 127) / 128, 256>>>(h, W2, xp2, N_NODES);
    attn2_kernel<<<(N_NODES * 32 + 255) / 256, 256>>>(att_src2, att_dst2);
    agg2_kernel<<<(N_NODES * 32 + 255) / 256, 256>>>(b2, out);
}

// round 7
// speedup vs baseline: 1.6379x; 1.0721x over previous
#include <cuda_runtime.h>
#include <math.h>

#define N_NODES 100000
#define E_EDGES 800000
#define ET (E_EDGES + N_NODES)   // edges + self loops = 900000
#define IN_CH 128
#define HID 32
#define HEADS 8
#define C1 (HEADS * HID)          // 256
#define OUT_CH 40
#define NEG_SLOPE 0.2f

// ---------------- scratch (device globals; no allocation allowed) ----------
__device__ float g_xp1[N_NODES * C1];
__device__ float g_h[N_NODES * C1];
__device__ float g_xp2[N_NODES * OUT_CH];
__device__ float g_as1[N_NODES * HEADS];
__device__ float g_ad1[N_NODES * HEADS];
__device__ float g_as2[N_NODES];
__device__ float g_ad2[N_NODES];

__device__ int g_deg[N_NODES];
__device__ int g_rowstart[N_NODES + 1];
__device__ int g_cursor[N_NODES];
__device__ int g_csrc[ET];

__device__ __forceinline__ float leaky(float x) {
    return x > 0.0f ? x : NEG_SLOPE * x;
}

// ================= CSR build =================================================
__global__ void zero_deg_kernel() {
    int i = blockIdx.x * blockDim.x + threadIdx.x;
    if (i < N_NODES) g_deg[i] = 0;
}

__global__ void hist_kernel(const int* __restrict__ ei) {
    int e = blockIdx.x * blockDim.x + threadIdx.x;
    if (e >= ET) return;
    int dst = (e < E_EDGES) ? ei[E_EDGES + e] : e - E_EDGES;
    atomicAdd(&g_deg[dst], 1);
}

__global__ void scan_kernel() {
    __shared__ int sums[1024];
    const int t = threadIdx.x;
    const int CH = (N_NODES + 1023) / 1024;
    int lo = t * CH;
    int hi = lo + CH; if (hi > N_NODES) hi = N_NODES;
    int s = 0;
    for (int i = lo; i < hi; i++) s += g_deg[i];
    sums[t] = s;
    __syncthreads();
    for (int o = 1; o < 1024; o <<= 1) {
        int u = (t >= o) ? sums[t - o] : 0;
        __syncthreads();
        sums[t] += u;
        __syncthreads();
    }
    int run = sums[t] - s;
    for (int i = lo; i < hi; i++) {
        g_rowstart[i] = run;
        g_cursor[i]   = run;
        run += g_deg[i];
    }
    if (t == 0) g_rowstart[N_NODES] = ET;
}

__global__ void scatter_kernel(const int* __restrict__ ei) {
    int e = blockIdx.x * blockDim.x + threadIdx.x;
    if (e >= ET) return;
    int src, dst;
    if (e < E_EDGES) { src = ei[e]; dst = ei[E_EDGES + e]; }
    else             { src = dst = e - E_EDGES; }
    int pos = atomicAdd(&g_cursor[dst], 1);
    g_csrc[pos] = src;
}

// ================= tf32 helpers =============================================
__device__ __forceinline__ unsigned tf32_of(float x) {
    unsigned r;
    asm("cvt.rna.tf32.f32 %0, %1;" : "=r"(r) : "f"(x));
    return r;
}
__device__ __forceinline__ void tf32_split(float x, unsigned& hi, unsigned& lo) {
    hi = tf32_of(x);
    float lo_f = x - __uint_as_float(hi);
    lo = tf32_of(lo_f);
}
__device__ __forceinline__ void mma_tf32(float* d, const unsigned* a, const unsigned* b) {
    asm volatile(
        "mma.sync.aligned.m16n8k8.row.col.f32.tf32.tf32.f32 "
        "{%0,%1,%2,%3}, {%4,%5,%6,%7}, {%8,%9}, {%0,%1,%2,%3};"
        : "+f"(d[0]), "+f"(d[1]), "+f"(d[2]), "+f"(d[3])
        : "r"(a[0]), "r"(a[1]), "r"(a[2]), "r"(a[3]), "r"(b[0]), "r"(b[1]));
}

// ============ GEMM1 (tensor core, tf32x3): C[M,256] = A[M,128] @ B[128,256] =
// BM=128, BN=128, BK=16, 256 threads (8 warps, 4x2), warp tile 32x64.
#define PAD 136
__global__ __launch_bounds__(256) void sgemm1_tc_kernel(const float* __restrict__ A,
                                                        const float* __restrict__ B,
                                                        float* __restrict__ C, int M) {
    __shared__ float As[2][16][PAD];
    __shared__ float Bs[2][16][PAD];

    const int tid  = threadIdx.x;
    const int wid  = tid >> 5;
    const int lane = tid & 31;
    const int warpM = wid & 3;           // 0..3 -> M offset *32
    const int warpN = wid >> 2;          // 0..1 -> N offset *64
    const int rowBase = blockIdx.y * 128;
    const int colBase = blockIdx.x * 128;

    const int r = lane >> 2;             // 0..7
    const int c = lane & 3;              // 0..3

    float acc[2][8][4];
#pragma unroll
    for (int i = 0; i < 2; i++)
#pragma unroll
        for (int j = 0; j < 8; j++)
#pragma unroll
            for (int q = 0; q < 4; q++) acc[i][j][q] = 0.0f;

    // gmem staging mapping: 512 float4 per tile, 2 per thread
    // A: q -> row = q>>2, kq = q&3 ; B: q -> k = q>>5, nq = q&31
    float4 avs[2], bvs[2];

    // prologue: stage 0
#pragma unroll
    for (int t = 0; t < 2; t++) {
        int q = tid + t * 256;
        int ar = q >> 2, akq = q & 3;
        int gr = rowBase + ar;
        avs[t] = make_float4(0.f, 0.f, 0.f, 0.f);
        if (gr < M) avs[t] = *(const float4*)&A[(long)gr * IN_CH + akq * 4];
        int bk = q >> 5, bnq = q & 31;
        bvs[t] = *(const float4*)&B[(long)bk * C1 + colBase + bnq * 4];
    }
#pragma unroll
    for (int t = 0; t < 2; t++) {
        int q = tid + t * 256;
        int ar = q >> 2, akq = q & 3;
        As[0][akq * 4 + 0][ar] = avs[t].x;
        As[0][akq * 4 + 1][ar] = avs[t].y;
        As[0][akq * 4 + 2][ar] = avs[t].z;
        As[0][akq * 4 + 3][ar] = avs[t].w;
        int bk = q >> 5, bnq = q & 31;
        *(float4*)&Bs[0][bk][bnq * 4] = bvs[t];
    }
    __syncthreads();

    int p = 0;
#pragma unroll
    for (int s = 0; s < 8; s++) {
        if (s < 7) {
            int k0 = (s + 1) * 16;
#pragma unroll
            for (int t = 0; t < 2; t++) {
                int q = tid + t * 256;
                int ar = q >> 2, akq = q & 3;
                int gr = rowBase + ar;
                avs[t] = make_float4(0.f, 0.f, 0.f, 0.f);
                if (gr < M) avs[t] = *(const float4*)&A[(long)gr * IN_CH + k0 + akq * 4];
                int bk = q >> 5, bnq = q & 31;
                bvs[t] = *(const float4*)&B[(long)(k0 + bk) * C1 + colBase + bnq * 4];
            }
        }
        // compute: two k8 halves from buffer p
#pragma unroll
        for (int kk = 0; kk < 16; kk += 8) {
            unsigned ah[2][4], al[2][4];
#pragma unroll
            for (int im = 0; im < 2; im++) {
                int mb = warpM * 32 + im * 16;
                float a0 = As[p][kk + c][mb + r];
                float a1 = As[p][kk + c][mb + 8 + r];
                float a2 = As[p][kk + 4 + c][mb + r];
                float a3 = As[p][kk + 4 + c][mb + 8 + r];
                tf32_split(a0, ah[im][0], al[im][0]);
                tf32_split(a1, ah[im][1], al[im][1]);
                tf32_split(a2, ah[im][2], al[im][2]);
                tf32_split(a3, ah[im][3], al[im][3]);
            }
            unsigned bh[8][2], bl[8][2];
#pragma unroll
            for (int in = 0; in < 8; in++) {
                int nb = warpN * 64 + in * 8 + r;
                float b0 = Bs[p][kk + c][nb];
                float b1 = Bs[p][kk + 4 + c][nb];
                tf32_split(b0, bh[in][0], bl[in][0]);
                tf32_split(b1, bh[in][1], bl[in][1]);
            }
#pragma unroll
            for (int im = 0; im < 2; im++)
#pragma unroll
                for (int in = 0; in < 8; in++) {
                    mma_tf32(acc[im][in], al[im], bh[in]);
                    mma_tf32(acc[im][in], ah[im], bl[in]);
                    mma_tf32(acc[im][in], ah[im], bh[in]);
                }
        }
        if (s < 7) {
            p ^= 1;
#pragma unroll
            for (int t = 0; t < 2; t++) {
                int q = tid + t * 256;
                int ar = q >> 2, akq = q & 3;
                As[p][akq * 4 + 0][ar] = avs[t].x;
                As[p][akq * 4 + 1][ar] = avs[t].y;
                As[p][akq * 4 + 2][ar] = avs[t].z;
                As[p][akq * 4 + 3][ar] = avs[t].w;
                int bk = q >> 5, bnq = q & 31;
                *(float4*)&Bs[p][bk][bnq * 4] = bvs[t];
            }
            __syncthreads();
        }
    }

    // epilogue: write C fragments
#pragma unroll
    for (int im = 0; im < 2; im++) {
        int row0 = rowBase + warpM * 32 + im * 16 + r;
        int row1 = row0 + 8;
#pragma unroll
        for (int in = 0; in < 8; in++) {
            int col = colBase + warpN * 64 + in * 8 + 2 * c;
            if (row0 < M)
                *(float2*)&C[(long)row0 * C1 + col] = make_float2(acc[im][in][0], acc[im][in][1]);
            if (row1 < M)
                *(float2*)&C[(long)row1 * C1 + col] = make_float2(acc[im][in][2], acc[im][in][3]);
        }
    }
}

// ============ GEMM2: C[M,40] = A[M,256] @ B[256,40] (FFMA) ==================
__global__ __launch_bounds__(256) void sgemm2_kernel(const float* __restrict__ A,
                                                     const float* __restrict__ B,
                                                     float* __restrict__ C, int M) {
    __shared__ float As[2][16][128];
    __shared__ float Bs[2][16][40];

    const int tid = threadIdx.x;
    const int rowBase = blockIdx.x * 128;

    const int arow = tid >> 1;
    const int akq  = (tid & 1) * 8;

    const int ty = tid >> 3;
    const int tx = tid & 7;

    float acc[4][5];
#pragma unroll
    for (int i = 0; i < 4; i++)
#pragma unroll
        for (int j = 0; j < 5; j++) acc[i][j] = 0.0f;

    const int gr = rowBase + arow;
    float4 av0, av1;
    float bsc[3];

    av0 = make_float4(0.f, 0.f, 0.f, 0.f);
    av1 = make_float4(0.f, 0.f, 0.f, 0.f);
    if (gr < M) {
        av0 = *(const float4*)&A[(long)gr * C1 + akq];
        av1 = *(const float4*)&A[(long)gr * C1 + akq + 4];
    }
#pragma unroll
    for (int t = 0; t < 3; t++) {
        int idx = tid + t * 256;
        bsc[t] = (idx < 16 * 40) ? B[(long)(idx / 40) * OUT_CH + idx % 40] : 0.f;
    }
    As[0][akq + 0][arow] = av0.x; As[0][akq + 1][arow] = av0.y;
    As[0][akq + 2][arow] = av0.z; As[0][akq + 3][arow] = av0.w;
    As[0][akq + 4][arow] = av1.x; As[0][akq + 5][arow] = av1.y;
    As[0][akq + 6][arow] = av1.z; As[0][akq + 7][arow] = av1.w;
#pragma unroll
    for (int t = 0; t < 3; t++) {
        int idx = tid + t * 256;
        if (idx < 16 * 40) Bs[0][idx / 40][idx % 40] = bsc[t];
    }
    __syncthreads();

    int p = 0;
#pragma unroll
    for (int s = 0; s < 16; s++) {
        if (s < 15) {
            int k0 = (s + 1) * 16;
            av0 = make_float4(0.f, 0.f, 0.f, 0.f);
            av1 = make_float4(0.f, 0.f, 0.f, 0.f);
            if (gr < M) {
                av0 = *(const float4*)&A[(long)gr * C1 + k0 + akq];
                av1 = *(const float4*)&A[(long)gr * C1 + k0 + akq + 4];
            }
#pragma unroll
            for (int t = 0; t < 3; t++) {
                int idx = tid + t * 256;
                bsc[t] = (idx < 16 * 40) ? B[(long)(k0 + idx / 40) * OUT_CH + idx % 40] : 0.f;
            }
        }
#pragma unroll
        for (int k = 0; k < 16; k++) {
            float a[4], b[5];
            *(float4*)&a[0] = *(const float4*)&As[p][k][ty * 4];
#pragma unroll
            for (int j = 0; j < 5; j++) b[j] = Bs[p][k][tx * 5 + j];
#pragma unroll
            for (int i = 0; i < 4; i++)
#pragma unroll
                for (int j = 0; j < 5; j++) acc[i][j] += a[i] * b[j];
        }
        if (s < 15) {
            p ^= 1;
            As[p][akq + 0][arow] = av0.x; As[p][akq + 1][arow] = av0.y;
            As[p][akq + 2][arow] = av0.z; As[p][akq + 3][arow] = av0.w;
            As[p][akq + 4][arow] = av1.x; As[p][akq + 5][arow] = av1.y;
            As[p][akq + 6][arow] = av1.z; As[p][akq + 7][arow] = av1.w;
#pragma unroll
            for (int t = 0; t < 3; t++) {
                int idx = tid + t * 256;
                if (idx < 16 * 40) Bs[p][idx / 40][idx % 40] = bsc[t];
            }
            __syncthreads();
        }
    }

#pragma unroll
    for (int i = 0; i < 4; i++) {
        int r = rowBase + ty * 4 + i;
        if (r >= M) continue;
#pragma unroll
        for (int j = 0; j < 5; j++) C[(long)r * OUT_CH + tx * 5 + j] = acc[i][j];
    }
}

// ---------------- attention coefficients, layer 1 (warp per node) -----------
__global__ void attn1_kernel(const float* __restrict__ att_src,
                             const float* __restrict__ att_dst) {
    int warp = (blockIdx.x * blockDim.x + threadIdx.x) >> 5;
    int lane = threadIdx.x & 31;
    if (warp >= N_NODES) return;
    const float* xp = &g_xp1[(long)warp * C1];
#pragma unroll
    for (int it = 0; it < 8; it++) {
        int c = it * 32 + lane;
        float v = xp[c];
        float ps = v * att_src[c];
        float pd = v * att_dst[c];
#pragma unroll
        for (int o = 16; o > 0; o >>= 1) {
            ps += __shfl_xor_sync(0xffffffffu, ps, o);
            pd += __shfl_xor_sync(0xffffffffu, pd, o);
        }
        if (lane == 0) {
            g_as1[warp * 8 + it] = ps;
            g_ad1[warp * 8 + it] = pd;
        }
    }
}

// ---------------- layer-1 aggregation: warp per dst node, no atomics --------
__global__ __launch_bounds__(256) void agg1_kernel(const float* __restrict__ b1) {
    int n = (blockIdx.x * blockDim.x + threadIdx.x) >> 5;
    int lane = threadIdx.x & 31;
    if (n >= N_NODES) return;
    const int start = g_rowstart[n];
    const int end   = g_rowstart[n + 1];

    const int h   = lane & 7;
    const int grp = lane >> 3;
    const float adv = g_ad1[n * 8 + h];

    float m = -INFINITY;
    for (int i = start + grp; i < end; i += 4) {
        int s = g_csrc[i];
        m = fmaxf(m, leaky(g_as1[s * 8 + h] + adv));
    }
    m = fmaxf(m, __shfl_xor_sync(0xffffffffu, m, 8));
    m = fmaxf(m, __shfl_xor_sync(0xffffffffu, m, 16));

    float acc[8] = {0.f, 0.f, 0.f, 0.f, 0.f, 0.f, 0.f, 0.f};
    float z = 0.f;
    for (int i = start; i < end; i++) {
        int s = g_csrc[i];
        float p = 0.f;
        if (lane < 8) {
            p = __expf(leaky(g_as1[s * 8 + lane] + adv) - m);
            z += p;
        }
        const float* xs = &g_xp1[(long)s * C1];
#pragma unroll
        for (int hh = 0; hh < 8; hh++) {
            float ph = __shfl_sync(0xffffffffu, p, hh);
            acc[hh] += ph * xs[hh * 32 + lane];
        }
    }

    float* hd = &g_h[(long)n * C1];
#pragma unroll
    for (int hh = 0; hh < 8; hh++) {
        float zh = __shfl_sync(0xffffffffu, z, hh);
        float v = acc[hh] / (zh + 1e-16f) + b1[hh * 32 + lane];
        hd[hh * 32 + lane] = fmaxf(v, 0.f);
    }
}

// ---------------- attention coefficients, layer 2 (warp per node) -----------
__global__ void attn2_kernel(const float* __restrict__ att_src,
                             const float* __restrict__ att_dst) {
    int warp = (blockIdx.x * blockDim.x + threadIdx.x) >> 5;
    int lane = threadIdx.x & 31;
    if (warp >= N_NODES) return;
    const float* xp = &g_xp2[(long)warp * OUT_CH];
    float v = xp[lane];
    float s = v * att_src[lane];
    float d = v * att_dst[lane];
    if (lane < 8) {
        float v2 = xp[32 + lane];
        s += v2 * att_src[32 + lane];
        d += v2 * att_dst[32 + lane];
    }
#pragma unroll
    for (int o = 16; o > 0; o >>= 1) {
        s += __shfl_xor_sync(0xffffffffu, s, o);
        d += __shfl_xor_sync(0xffffffffu, d, o);
    }
    if (lane == 0) { g_as2[warp] = s; g_ad2[warp] = d; }
}

// ---------- layer-2 aggregation + log_softmax: warp per dst node ------------
__global__ __launch_bounds__(256) void agg2_kernel(const float* __restrict__ b2,
                                                   float* __restrict__ out) {
    int n = (blockIdx.x * blockDim.x + threadIdx.x) >> 5;
    int lane = threadIdx.x & 31;
    if (n >= N_NODES) return;
    const int start = g_rowstart[n];
    const int end   = g_rowstart[n + 1];
    const float adn = g_ad2[n];

    float m = -INFINITY;
    for (int i = start + lane; i < end; i += 32)
        m = fmaxf(m, leaky(g_as2[g_csrc[i]] + adn));
#pragma unroll
    for (int o = 16; o > 0; o >>= 1)
        m = fmaxf(m, __shfl_xor_sync(0xffffffffu, m, o));

    float a0 = 0.f, a1 = 0.f, z = 0.f;
    for (int i = start; i < end; i++) {
        int s = g_csrc[i];
        float p = __expf(leaky(g_as2[s] + adn) - m);
        z += p;
        const float* xs = &g_xp2[(long)s * OUT_CH];
        a0 += p * xs[lane];
        if (lane < 8) a1 += p * xs[32 + lane];
    }
    float zi = 1.0f / (z + 1e-16f);

    float x1 = a0 * zi + b2[lane];
    float x2 = (lane < 8) ? (a1 * zi + b2[32 + lane]) : -INFINITY;
    float mx = fmaxf(x1, x2);
#pragma unroll
    for (int o = 16; o > 0; o >>= 1) mx = fmaxf(mx, __shfl_xor_sync(0xffffffffu, mx, o));
    float se = __expf(x1 - mx) + ((lane < 8) ? __expf(x2 - mx) : 0.0f);
#pragma unroll
    for (int o = 16; o > 0; o >>= 1) se += __shfl_xor_sync(0xffffffffu, se, o);
    float lse = mx + logf(se);
    out[(long)n * OUT_CH + lane] = x1 - lse;
    if (lane < 8) out[(long)n * OUT_CH + 32 + lane] = x2 - lse;
}

// ---------------- launch ----------------------------------------------------
extern "C" void kernel_launch(void* const* d_in, const int* in_sizes, int n_in,
                              void* d_out, int out_size) {
    const float* x        = (const float*)d_in[0];
    const int*   ei       = (const int*)d_in[1];
    const float* W1       = (const float*)d_in[2];
    const float* att_src1 = (const float*)d_in[3];
    const float* att_dst1 = (const float*)d_in[4];
    const float* b1       = (const float*)d_in[5];
    const float* W2       = (const float*)d_in[6];
    const float* att_src2 = (const float*)d_in[7];
    const float* att_dst2 = (const float*)d_in[8];
    const float* b2       = (const float*)d_in[9];
    float*       out      = (float*)d_out;

    float* xp1 = nullptr; float* h = nullptr; float* xp2 = nullptr;
    cudaGetSymbolAddress((void**)&xp1, g_xp1);
    cudaGetSymbolAddress((void**)&h,   g_h);
    cudaGetSymbolAddress((void**)&xp2, g_xp2);

    // CSR build (shared by both layers)
    zero_deg_kernel<<<(N_NODES + 255) / 256, 256>>>();
    hist_kernel<<<(ET + 255) / 256, 256>>>(ei);
    scan_kernel<<<1, 1024>>>();
    scatter_kernel<<<(ET + 255) / 256, 256>>>(ei);

    // layer 1
    {
        dim3 grid(C1 / 128, (N_NODES + 127) / 128);
        sgemm1_tc_kernel<<<grid, 256>>>(x, W1, xp1, N_NODES);
    }
    attn1_kernel<<<(N_NODES * 32 + 255) / 256, 256>>>(att_src1, att_dst1);
    agg1_kernel<<<(N_NODES * 32 + 255) / 256, 256>>>(b1);

    // layer 2
    sgemm2_kernel<<<(N_NODES + 127) / 128, 256>>>(h, W2, xp2, N_NODES);
    attn2_kernel<<<(N_NODES * 32 + 255) / 256, 256>>>(att_src2, att_dst2);
    agg2_kernel<<<(N_NODES * 32 + 255) / 256, 256>>>(b2, out);
}

// round 8
// speedup vs baseline: 1.6983x; 1.0369x over previous
#include <cuda_runtime.h>
#include <math.h>

#define N_NODES 100000
#define E_EDGES 800000
#define ET (E_EDGES + N_NODES)   // edges + self loops = 900000
#define IN_CH 128
#define HID 32
#define HEADS 8
#define C1 (HEADS * HID)          // 256
#define OUT_CH 40
#define NEG_SLOPE 0.2f

// ---------------- scratch (device globals; no allocation allowed) ----------
__device__ float g_xp1[N_NODES * C1];
__device__ float g_h[N_NODES * C1];
__device__ float g_xp2[N_NODES * OUT_CH];
__device__ float g_as1[N_NODES * HEADS];
__device__ float g_ad1[N_NODES * HEADS];
__device__ float g_as2[N_NODES];
__device__ float g_ad2[N_NODES];

__device__ int g_deg[N_NODES];
__device__ int g_rowstart[N_NODES + 1];
__device__ int g_cursor[N_NODES];
__device__ int g_csrc[ET];

__device__ __forceinline__ float leaky(float x) {
    return x > 0.0f ? x : NEG_SLOPE * x;
}

// ================= CSR build =================================================
__global__ void zero_deg_kernel() {
    int i = blockIdx.x * blockDim.x + threadIdx.x;
    if (i < N_NODES) g_deg[i] = 0;
}

__global__ void hist_kernel(const int* __restrict__ ei) {
    int e = blockIdx.x * blockDim.x + threadIdx.x;
    if (e >= ET) return;
    int dst = (e < E_EDGES) ? ei[E_EDGES + e] : e - E_EDGES;
    atomicAdd(&g_deg[dst], 1);
}

__global__ void scan_kernel() {
    __shared__ int sums[1024];
    const int t = threadIdx.x;
    const int CH = (N_NODES + 1023) / 1024;
    int lo = t * CH;
    int hi = lo + CH; if (hi > N_NODES) hi = N_NODES;
    int s = 0;
    for (int i = lo; i < hi; i++) s += g_deg[i];
    sums[t] = s;
    __syncthreads();
    for (int o = 1; o < 1024; o <<= 1) {
        int u = (t >= o) ? sums[t - o] : 0;
        __syncthreads();
        sums[t] += u;
        __syncthreads();
    }
    int run = sums[t] - s;
    for (int i = lo; i < hi; i++) {
        g_rowstart[i] = run;
        g_cursor[i]   = run;
        run += g_deg[i];
    }
    if (t == 0) g_rowstart[N_NODES] = ET;
}

__global__ void scatter_kernel(const int* __restrict__ ei) {
    int e = blockIdx.x * blockDim.x + threadIdx.x;
    if (e >= ET) return;
    int src, dst;
    if (e < E_EDGES) { src = ei[e]; dst = ei[E_EDGES + e]; }
    else             { src = dst = e - E_EDGES; }
    int pos = atomicAdd(&g_cursor[dst], 1);
    g_csrc[pos] = src;
}

// ================= tf32 helpers =============================================
__device__ __forceinline__ unsigned tf32_of(float x) {
    unsigned r;
    asm("cvt.rna.tf32.f32 %0, %1;" : "=r"(r) : "f"(x));
    return r;
}
__device__ __forceinline__ void tf32_split(float x, unsigned& hi, unsigned& lo) {
    hi = tf32_of(x);
    float lo_f = x - __uint_as_float(hi);
    lo = tf32_of(lo_f);
}
__device__ __forceinline__ void tf32_split_f(float x, float& hi, float& lo) {
    unsigned h, l;
    tf32_split(x, h, l);
    hi = __uint_as_float(h);
    lo = __uint_as_float(l);
}
__device__ __forceinline__ void mma_tf32(float* d, const unsigned* a, const unsigned* b) {
    asm volatile(
        "mma.sync.aligned.m16n8k8.row.col.f32.tf32.tf32.f32 "
        "{%0,%1,%2,%3}, {%4,%5,%6,%7}, {%8,%9}, {%0,%1,%2,%3};"
        : "+f"(d[0]), "+f"(d[1]), "+f"(d[2]), "+f"(d[3])
        : "r"(a[0]), "r"(a[1]), "r"(a[2]), "r"(a[3]), "r"(b[0]), "r"(b[1]));
}

#define PAD 136

// ============ GEMM1 (tc tf32x3, pre-split smem): C[M,256] = A[M,128]@B[128,256]
// BM=128, BN=128, BK=8, 256 threads (8 warps 4x2), warp tile 32x64, dbl-buffered.
__global__ __launch_bounds__(256) void sgemm1_tc_kernel(const float* __restrict__ A,
                                                        const float* __restrict__ B,
                                                        float* __restrict__ C, int M) {
    __shared__ __align__(16) float AsH[2][8][PAD];
    __shared__ __align__(16) float AsL[2][8][PAD];
    __shared__ __align__(16) float BsH[2][8][PAD];
    __shared__ __align__(16) float BsL[2][8][PAD];

    const int tid  = threadIdx.x;
    const int wid  = tid >> 5;
    const int lane = tid & 31;
    const int warpM = wid & 3;
    const int warpN = wid >> 2;
    const int rowBase = blockIdx.y * 128;
    const int colBase = blockIdx.x * 128;

    const int r = lane >> 2;
    const int c = lane & 3;

    float acc[2][8][4];
#pragma unroll
    for (int i = 0; i < 2; i++)
#pragma unroll
        for (int j = 0; j < 8; j++)
#pragma unroll
            for (int q = 0; q < 4; q++) acc[i][j][q] = 0.0f;

    // loader mapping: 1 float4 of A and 1 of B per thread per stage
    const int ar  = tid >> 1;            // 0..127
    const int akq = (tid & 1) * 4;       // 0 or 4
    const int bk  = tid >> 5;            // 0..7
    const int bnq = (tid & 31) * 4;      // 0..124
    const int gr  = rowBase + ar;

    float4 av, bv;

    // prologue: stage 0
    av = make_float4(0.f, 0.f, 0.f, 0.f);
    if (gr < M) av = *(const float4*)&A[(long)gr * IN_CH + akq];
    bv = *(const float4*)&B[(long)bk * C1 + colBase + bnq];
    {
        float ah_, al_;
        tf32_split_f(av.x, ah_, al_); AsH[0][akq + 0][ar] = ah_; AsL[0][akq + 0][ar] = al_;
        tf32_split_f(av.y, ah_, al_); AsH[0][akq + 1][ar] = ah_; AsL[0][akq + 1][ar] = al_;
        tf32_split_f(av.z, ah_, al_); AsH[0][akq + 2][ar] = ah_; AsL[0][akq + 2][ar] = al_;
        tf32_split_f(av.w, ah_, al_); AsH[0][akq + 3][ar] = ah_; AsL[0][akq + 3][ar] = al_;
        float4 hv, lv;
        tf32_split_f(bv.x, hv.x, lv.x);
        tf32_split_f(bv.y, hv.y, lv.y);
        tf32_split_f(bv.z, hv.z, lv.z);
        tf32_split_f(bv.w, hv.w, lv.w);
        *(float4*)&BsH[0][bk][bnq] = hv;
        *(float4*)&BsL[0][bk][bnq] = lv;
    }
    __syncthreads();

    int p = 0;
#pragma unroll
    for (int s = 0; s < 16; s++) {
        if (s < 15) {
            int k0 = (s + 1) * 8;
            av = make_float4(0.f, 0.f, 0.f, 0.f);
            if (gr < M) av = *(const float4*)&A[(long)gr * IN_CH + k0 + akq];
            bv = *(const float4*)&B[(long)(k0 + bk) * C1 + colBase + bnq];
        }
        // compute stage p (pure LDS + MMA)
        {
            unsigned ah[2][4], al[2][4];
#pragma unroll
            for (int im = 0; im < 2; im++) {
                int mb = warpM * 32 + im * 16;
                ah[im][0] = __float_as_uint(AsH[p][c][mb + r]);
                ah[im][1] = __float_as_uint(AsH[p][c][mb + 8 + r]);
                ah[im][2] = __float_as_uint(AsH[p][4 + c][mb + r]);
                ah[im][3] = __float_as_uint(AsH[p][4 + c][mb + 8 + r]);
                al[im][0] = __float_as_uint(AsL[p][c][mb + r]);
                al[im][1] = __float_as_uint(AsL[p][c][mb + 8 + r]);
                al[im][2] = __float_as_uint(AsL[p][4 + c][mb + r]);
                al[im][3] = __float_as_uint(AsL[p][4 + c][mb + 8 + r]);
            }
            unsigned bh[8][2], bl[8][2];
#pragma unroll
            for (int in = 0; in < 8; in++) {
                int nb = warpN * 64 + in * 8 + r;
                bh[in][0] = __float_as_uint(BsH[p][c][nb]);
                bh[in][1] = __float_as_uint(BsH[p][4 + c][nb]);
                bl[in][0] = __float_as_uint(BsL[p][c][nb]);
                bl[in][1] = __float_as_uint(BsL[p][4 + c][nb]);
            }
#pragma unroll
            for (int im = 0; im < 2; im++)
#pragma unroll
                for (int in = 0; in < 8; in++) {
                    mma_tf32(acc[im][in], al[im], bh[in]);
                    mma_tf32(acc[im][in], ah[im], bl[in]);
                    mma_tf32(acc[im][in], ah[im], bh[in]);
                }
        }
        if (s < 15) {
            p ^= 1;
            float ah_, al_;
            tf32_split_f(av.x, ah_, al_); AsH[p][akq + 0][ar] = ah_; AsL[p][akq + 0][ar] = al_;
            tf32_split_f(av.y, ah_, al_); AsH[p][akq + 1][ar] = ah_; AsL[p][akq + 1][ar] = al_;
            tf32_split_f(av.z, ah_, al_); AsH[p][akq + 2][ar] = ah_; AsL[p][akq + 2][ar] = al_;
            tf32_split_f(av.w, ah_, al_); AsH[p][akq + 3][ar] = ah_; AsL[p][akq + 3][ar] = al_;
            float4 hv, lv;
            tf32_split_f(bv.x, hv.x, lv.x);
            tf32_split_f(bv.y, hv.y, lv.y);
            tf32_split_f(bv.z, hv.z, lv.z);
            tf32_split_f(bv.w, hv.w, lv.w);
            *(float4*)&BsH[p][bk][bnq] = hv;
            *(float4*)&BsL[p][bk][bnq] = lv;
            __syncthreads();
        }
    }

    // epilogue
#pragma unroll
    for (int im = 0; im < 2; im++) {
        int row0 = rowBase + warpM * 32 + im * 16 + r;
        int row1 = row0 + 8;
#pragma unroll
        for (int in = 0; in < 8; in++) {
            int col = colBase + warpN * 64 + in * 8 + 2 * c;
            if (row0 < M)
                *(float2*)&C[(long)row0 * C1 + col] = make_float2(acc[im][in][0], acc[im][in][1]);
            if (row1 < M)
                *(float2*)&C[(long)row1 * C1 + col] = make_float2(acc[im][in][2], acc[im][in][3]);
        }
    }
}

// ============ GEMM2 (tc tf32x3): C[M,40] = A[M,256] @ B[256,40] =============
// BM=128, BN=40, BK=16, 256 threads; warp w owns rows w*16..w*16+15, 5 n8 frags.
__global__ __launch_bounds__(256) void sgemm2_tc_kernel(const float* __restrict__ A,
                                                        const float* __restrict__ B,
                                                        float* __restrict__ C, int M) {
    __shared__ __align__(16) float As[2][16][PAD];
    __shared__ float BsH[2][16][40];
    __shared__ float BsL[2][16][40];

    const int tid  = threadIdx.x;
    const int wid  = tid >> 5;
    const int lane = tid & 31;
    const int rowBase = blockIdx.x * 128;
    const int r = lane >> 2;
    const int c = lane & 3;

    float acc[5][4];
#pragma unroll
    for (int j = 0; j < 5; j++)
#pragma unroll
        for (int q = 0; q < 4; q++) acc[j][q] = 0.0f;

    float4 avs[2];
    float  bsc[3];

    // prologue: stage 0 (k0 = 0)
#pragma unroll
    for (int t = 0; t < 2; t++) {
        int q = tid + t * 256;
        int ar = q >> 2, akq = q & 3;
        int gr = rowBase + ar;
        avs[t] = make_float4(0.f, 0.f, 0.f, 0.f);
        if (gr < M) avs[t] = *(const float4*)&A[(long)gr * C1 + akq * 4];
    }
#pragma unroll
    for (int t = 0; t < 3; t++) {
        int idx = tid + t * 256;
        bsc[t] = (idx < 16 * 40) ? B[(long)(idx / 40) * OUT_CH + idx % 40] : 0.f;
    }
#pragma unroll
    for (int t = 0; t < 2; t++) {
        int q = tid + t * 256;
        int ar = q >> 2, akq = q & 3;
        As[0][akq * 4 + 0][ar] = avs[t].x;
        As[0][akq * 4 + 1][ar] = avs[t].y;
        As[0][akq * 4 + 2][ar] = avs[t].z;
        As[0][akq * 4 + 3][ar] = avs[t].w;
    }
#pragma unroll
    for (int t = 0; t < 3; t++) {
        int idx = tid + t * 256;
        if (idx < 16 * 40) {
            float h_, l_;
            tf32_split_f(bsc[t], h_, l_);
            BsH[0][idx / 40][idx % 40] = h_;
            BsL[0][idx / 40][idx % 40] = l_;
        }
    }
    __syncthreads();

    int p = 0;
#pragma unroll
    for (int s = 0; s < 16; s++) {
        if (s < 15) {
            int k0 = (s + 1) * 16;
#pragma unroll
            for (int t = 0; t < 2; t++) {
                int q = tid + t * 256;
                int ar = q >> 2, akq = q & 3;
                int gr = rowBase + ar;
                avs[t] = make_float4(0.f, 0.f, 0.f, 0.f);
                if (gr < M) avs[t] = *(const float4*)&A[(long)gr * C1 + k0 + akq * 4];
            }
#pragma unroll
            for (int t = 0; t < 3; t++) {
                int idx = tid + t * 256;
                bsc[t] = (idx < 16 * 40) ? B[(long)(k0 + idx / 40) * OUT_CH + idx % 40] : 0.f;
            }
        }
        // compute stage p: two k8 halves
#pragma unroll
        for (int kk = 0; kk < 16; kk += 8) {
            unsigned ah[4], al[4];
            {
                int mb = wid * 16;
                tf32_split(As[p][kk + c][mb + r],         ah[0], al[0]);
                tf32_split(As[p][kk + c][mb + 8 + r],     ah[1], al[1]);
                tf32_split(As[p][kk + 4 + c][mb + r],     ah[2], al[2]);
                tf32_split(As[p][kk + 4 + c][mb + 8 + r], ah[3], al[3]);
            }
#pragma unroll
            for (int in = 0; in < 5; in++) {
                int nb = in * 8 + r;
                unsigned bh[2], bl[2];
                bh[0] = __float_as_uint(BsH[p][kk + c][nb]);
                bh[1] = __float_as_uint(BsH[p][kk + 4 + c][nb]);
                bl[0] = __float_as_uint(BsL[p][kk + c][nb]);
                bl[1] = __float_as_uint(BsL[p][kk + 4 + c][nb]);
                mma_tf32(acc[in], al, bh);
                mma_tf32(acc[in], ah, bl);
                mma_tf32(acc[in], ah, bh);
            }
        }
        if (s < 15) {
            p ^= 1;
#pragma unroll
            for (int t = 0; t < 2; t++) {
                int q = tid + t * 256;
                int ar = q >> 2, akq = q & 3;
                As[p][akq * 4 + 0][ar] = avs[t].x;
                As[p][akq * 4 + 1][ar] = avs[t].y;
                As[p][akq * 4 + 2][ar] = avs[t].z;
                As[p][akq * 4 + 3][ar] = avs[t].w;
            }
#pragma unroll
            for (int t = 0; t < 3; t++) {
                int idx = tid + t * 256;
                if (idx < 16 * 40) {
                    float h_, l_;
                    tf32_split_f(bsc[t], h_, l_);
                    BsH[p][idx / 40][idx % 40] = h_;
                    BsL[p][idx / 40][idx % 40] = l_;
                }
            }
            __syncthreads();
        }
    }

    // epilogue
    {
        int row0 = rowBase + wid * 16 + r;
        int row1 = row0 + 8;
#pragma unroll
        for (int in = 0; in < 5; in++) {
            int col = in * 8 + 2 * c;
            if (row0 < M)
                *(float2*)&C[(long)row0 * OUT_CH + col] = make_float2(acc[in][0], acc[in][1]);
            if (row1 < M)
                *(float2*)&C[(long)row1 * OUT_CH + col] = make_float2(acc[in][2], acc[in][3]);
        }
    }
}

// ---------------- attention coefficients, layer 1 (warp per node) -----------
__global__ void attn1_kernel(const float* __restrict__ att_src,
                             const float* __restrict__ att_dst) {
    int warp = (blockIdx.x * blockDim.x + threadIdx.x) >> 5;
    int lane = threadIdx.x & 31;
    if (warp >= N_NODES) return;
    const float* xp = &g_xp1[(long)warp * C1];
#pragma unroll
    for (int it = 0; it < 8; it++) {
        int c = it * 32 + lane;
        float v = xp[c];
        float ps = v * att_src[c];
        float pd = v * att_dst[c];
#pragma unroll
        for (int o = 16; o > 0; o >>= 1) {
            ps += __shfl_xor_sync(0xffffffffu, ps, o);
            pd += __shfl_xor_sync(0xffffffffu, pd, o);
        }
        if (lane == 0) {
            g_as1[warp * 8 + it] = ps;
            g_ad1[warp * 8 + it] = pd;
        }
    }
}

// ---------------- layer-1 aggregation: warp per dst node, no atomics --------
__global__ __launch_bounds__(256) void agg1_kernel(const float* __restrict__ b1) {
    int n = (blockIdx.x * blockDim.x + threadIdx.x) >> 5;
    int lane = threadIdx.x & 31;
    if (n >= N_NODES) return;
    const int start = g_rowstart[n];
    const int end   = g_rowstart[n + 1];

    const int h   = lane & 7;
    const int grp = lane >> 3;
    const float adv = g_ad1[n * 8 + h];

    float m = -INFINITY;
    for (int i = start + grp; i < end; i += 4) {
        int s = g_csrc[i];
        m = fmaxf(m, leaky(g_as1[s * 8 + h] + adv));
    }
    m = fmaxf(m, __shfl_xor_sync(0xffffffffu, m, 8));
    m = fmaxf(m, __shfl_xor_sync(0xffffffffu, m, 16));

    float acc[8] = {0.f, 0.f, 0.f, 0.f, 0.f, 0.f, 0.f, 0.f};
    float z = 0.f;
    for (int i = start; i < end; i++) {
        int s = g_csrc[i];
        float p = 0.f;
        if (lane < 8) {
            p = __expf(leaky(g_as1[s * 8 + lane] + adv) - m);
            z += p;
        }
        const float* xs = &g_xp1[(long)s * C1];
#pragma unroll
        for (int hh = 0; hh < 8; hh++) {
            float ph = __shfl_sync(0xffffffffu, p, hh);
            acc[hh] += ph * xs[hh * 32 + lane];
        }
    }

    float* hd = &g_h[(long)n * C1];
#pragma unroll
    for (int hh = 0; hh < 8; hh++) {
        float zh = __shfl_sync(0xffffffffu, z, hh);
        float v = acc[hh] / (zh + 1e-16f) + b1[hh * 32 + lane];
        hd[hh * 32 + lane] = fmaxf(v, 0.f);
    }
}

// ---------------- attention coefficients, layer 2 (warp per node) -----------
__global__ void attn2_kernel(const float* __restrict__ att_src,
                             const float* __restrict__ att_dst) {
    int warp = (blockIdx.x * blockDim.x + threadIdx.x) >> 5;
    int lane = threadIdx.x & 31;
    if (warp >= N_NODES) return;
    const float* xp = &g_xp2[(long)warp * OUT_CH];
    float v = xp[lane];
    float s = v * att_src[lane];
    float d = v * att_dst[lane];
    if (lane < 8) {
        float v2 = xp[32 + lane];
        s += v2 * att_src[32 + lane];
        d += v2 * att_dst[32 + lane];
    }
#pragma unroll
    for (int o = 16; o > 0; o >>= 1) {
        s += __shfl_xor_sync(0xffffffffu, s, o);
        d += __shfl_xor_sync(0xffffffffu, d, o);
    }
    if (lane == 0) { g_as2[warp] = s; g_ad2[warp] = d; }
}

// ---------- layer-2 aggregation + log_softmax: warp per dst node ------------
__global__ __launch_bounds__(256) void agg2_kernel(const float* __restrict__ b2,
                                                   float* __restrict__ out) {
    int n = (blockIdx.x * blockDim.x + threadIdx.x) >> 5;
    int lane = threadIdx.x & 31;
    if (n >= N_NODES) return;
    const int start = g_rowstart[n];
    const int end   = g_rowstart[n + 1];
    const float adn = g_ad2[n];

    float m = -INFINITY;
    for (int i = start + lane; i < end; i += 32)
        m = fmaxf(m, leaky(g_as2[g_csrc[i]] + adn));
#pragma unroll
    for (int o = 16; o > 0; o >>= 1)
        m = fmaxf(m, __shfl_xor_sync(0xffffffffu, m, o));

    float a0 = 0.f, a1 = 0.f, z = 0.f;
    for (int i = start; i < end; i++) {
        int s = g_csrc[i];
        float p = __expf(leaky(g_as2[s] + adn) - m);
        z += p;
        const float* xs = &g_xp2[(long)s * OUT_CH];
        a0 += p * xs[lane];
        if (lane < 8) a1 += p * xs[32 + lane];
    }
    float zi = 1.0f / (z + 1e-16f);

    float x1 = a0 * zi + b2[lane];
    float x2 = (lane < 8) ? (a1 * zi + b2[32 + lane]) : -INFINITY;
    float mx = fmaxf(x1, x2);
#pragma unroll
    for (int o = 16; o > 0; o >>= 1) mx = fmaxf(mx, __shfl_xor_sync(0xffffffffu, mx, o));
    float se = __expf(x1 - mx) + ((lane < 8) ? __expf(x2 - mx) : 0.0f);
#pragma unroll
    for (int o = 16; o > 0; o >>= 1) se += __shfl_xor_sync(0xffffffffu, se, o);
    float lse = mx + logf(se);
    out[(long)n * OUT_CH + lane] = x1 - lse;
    if (lane < 8) out[(long)n * OUT_CH + 32 + lane] = x2 - lse;
}

// ---------------- launch ----------------------------------------------------
extern "C" void kernel_launch(void* const* d_in, const int* in_sizes, int n_in,
                              void* d_out, int out_size) {
    const float* x        = (const float*)d_in[0];
    const int*   ei       = (const int*)d_in[1];
    const float* W1       = (const float*)d_in[2];
    const float* att_src1 = (const float*)d_in[3];
    const float* att_dst1 = (const float*)d_in[4];
    const float* b1       = (const float*)d_in[5];
    const float* W2       = (const float*)d_in[6];
    const float* att_src2 = (const float*)d_in[7];
    const float* att_dst2 = (const float*)d_in[8];
    const float* b2       = (const float*)d_in[9];
    float*       out      = (float*)d_out;

    float* xp1 = nullptr; float* h = nullptr; float* xp2 = nullptr;
    cudaGetSymbolAddress((void**)&xp1, g_xp1);
    cudaGetSymbolAddress((void**)&h,   g_h);
    cudaGetSymbolAddress((void**)&xp2, g_xp2);

    // CSR build (shared by both layers)
    zero_deg_kernel<<<(N_NODES + 255) / 256, 256>>>();
    hist_kernel<<<(ET + 255) / 256, 256>>>(ei);
    scan_kernel<<<1, 1024>>>();
    scatter_kernel<<<(ET + 255) / 256, 256>>>(ei);

    // layer 1
    {
        dim3 grid(C1 / 128, (N_NODES + 127) / 128);
        sgemm1_tc_kernel<<<grid, 256>>>(x, W1, xp1, N_NODES);
    }
    attn1_kernel<<<(N_NODES * 32 + 255) / 256, 256>>>(att_src1, att_dst1);
    agg1_kernel<<<(N_NODES * 32 + 255) / 256, 256>>>(b1);

    // layer 2
    sgemm2_tc_kernel<<<(N_NODES + 127) / 128, 256>>>(h, W2, xp2, N_NODES);
    attn2_kernel<<<(N_NODES * 32 + 255) / 256, 256>>>(att_src2, att_dst2);
    agg2_kernel<<<(N_NODES * 32 + 255) / 256, 256>>>(b2, out);
}

// round 9
// speedup vs baseline: 1.8192x; 1.0712x over previous
#include <cuda_runtime.h>
#include <cuda_fp16.h>
#include <math.h>

#define N_NODES 100000
#define E_EDGES 800000
#define ET (E_EDGES + N_NODES)   // edges + self loops = 900000
#define IN_CH 128
#define HID 32
#define HEADS 8
#define C1 (HEADS * HID)          // 256
#define OUT_CH 40
#define NEG_SLOPE 0.2f

// ---------------- scratch (device globals; no allocation allowed) ----------
__device__ float  g_xp1[N_NODES * C1];
__device__ __half g_xp1h[N_NODES * C1];   // fp16 mirror for the edge gather
__device__ float  g_h[N_NODES * C1];
__device__ float  g_xp2[N_NODES * OUT_CH];
__device__ float  g_as1[N_NODES * HEADS];
__device__ float  g_ad1[N_NODES * HEADS];
__device__ float  g_as2[N_NODES];
__device__ float  g_ad2[N_NODES];

__device__ int g_deg[N_NODES];
__device__ int g_rowstart[N_NODES + 1];
__device__ int g_cursor[N_NODES];
__device__ int g_csrc[ET];

__device__ __forceinline__ float leaky(float x) {
    return x > 0.0f ? x : NEG_SLOPE * x;
}

// ================= CSR build =================================================
__global__ void zero_deg_kernel() {
    int i = blockIdx.x * blockDim.x + threadIdx.x;
    if (i < N_NODES) g_deg[i] = 0;
}

__global__ void hist_kernel(const int* __restrict__ ei) {
    int e = blockIdx.x * blockDim.x + threadIdx.x;
    if (e >= ET) return;
    int dst = (e < E_EDGES) ? ei[E_EDGES + e] : e - E_EDGES;
    atomicAdd(&g_deg[dst], 1);
}

__global__ void scan_kernel() {
    __shared__ int sums[1024];
    const int t = threadIdx.x;
    const int CH = (N_NODES + 1023) / 1024;
    int lo = t * CH;
    int hi = lo + CH; if (hi > N_NODES) hi = N_NODES;
    int s = 0;
    for (int i = lo; i < hi; i++) s += g_deg[i];
    sums[t] = s;
    __syncthreads();
    for (int o = 1; o < 1024; o <<= 1) {
        int u = (t >= o) ? sums[t - o] : 0;
        __syncthreads();
        sums[t] += u;
        __syncthreads();
    }
    int run = sums[t] - s;
    for (int i = lo; i < hi; i++) {
        g_rowstart[i] = run;
        g_cursor[i]   = run;
        run += g_deg[i];
    }
    if (t == 0) g_rowstart[N_NODES] = ET;
}

__global__ void scatter_kernel(const int* __restrict__ ei) {
    int e = blockIdx.x * blockDim.x + threadIdx.x;
    if (e >= ET) return;
    int src, dst;
    if (e < E_EDGES) { src = ei[e]; dst = ei[E_EDGES + e]; }
    else             { src = dst = e - E_EDGES; }
    int pos = atomicAdd(&g_cursor[dst], 1);
    g_csrc[pos] = src;
}

// ================= tf32 helpers =============================================
__device__ __forceinline__ unsigned tf32_of(float x) {
    unsigned r;
    asm("cvt.rna.tf32.f32 %0, %1;" : "=r"(r) : "f"(x));
    return r;
}
__device__ __forceinline__ void tf32_split(float x, unsigned& hi, unsigned& lo) {
    hi = tf32_of(x);
    float lo_f = x - __uint_as_float(hi);
    lo = tf32_of(lo_f);
}
__device__ __forceinline__ void tf32_split_f(float x, float& hi, float& lo) {
    unsigned h, l;
    tf32_split(x, h, l);
    hi = __uint_as_float(h);
    lo = __uint_as_float(l);
}
__device__ __forceinline__ void mma_tf32(float* d, const unsigned* a, const unsigned* b) {
    asm volatile(
        "mma.sync.aligned.m16n8k8.row.col.f32.tf32.tf32.f32 "
        "{%0,%1,%2,%3}, {%4,%5,%6,%7}, {%8,%9}, {%0,%1,%2,%3};"
        : "+f"(d[0]), "+f"(d[1]), "+f"(d[2]), "+f"(d[3])
        : "r"(a[0]), "r"(a[1]), "r"(a[2]), "r"(a[3]), "r"(b[0]), "r"(b[1]));
}

#define PAD 136

// ============ GEMM1 (tc tf32x3, pre-split smem): C[M,256] = A[M,128]@B[128,256]
// Also writes the fp16 mirror g_xp1h in the epilogue.
__global__ __launch_bounds__(256) void sgemm1_tc_kernel(const float* __restrict__ A,
                                                        const float* __restrict__ B,
                                                        float* __restrict__ C, int M) {
    __shared__ __align__(16) float AsH[2][8][PAD];
    __shared__ __align__(16) float AsL[2][8][PAD];
    __shared__ __align__(16) float BsH[2][8][PAD];
    __shared__ __align__(16) float BsL[2][8][PAD];

    const int tid  = threadIdx.x;
    const int wid  = tid >> 5;
    const int lane = tid & 31;
    const int warpM = wid & 3;
    const int warpN = wid >> 2;
    const int rowBase = blockIdx.y * 128;
    const int colBase = blockIdx.x * 128;

    const int r = lane >> 2;
    const int c = lane & 3;

    float acc[2][8][4];
#pragma unroll
    for (int i = 0; i < 2; i++)
#pragma unroll
        for (int j = 0; j < 8; j++)
#pragma unroll
            for (int q = 0; q < 4; q++) acc[i][j][q] = 0.0f;

    const int ar  = tid >> 1;
    const int akq = (tid & 1) * 4;
    const int bk  = tid >> 5;
    const int bnq = (tid & 31) * 4;
    const int gr  = rowBase + ar;

    float4 av, bv;

    av = make_float4(0.f, 0.f, 0.f, 0.f);
    if (gr < M) av = *(const float4*)&A[(long)gr * IN_CH + akq];
    bv = *(const float4*)&B[(long)bk * C1 + colBase + bnq];
    {
        float ah_, al_;
        tf32_split_f(av.x, ah_, al_); AsH[0][akq + 0][ar] = ah_; AsL[0][akq + 0][ar] = al_;
        tf32_split_f(av.y, ah_, al_); AsH[0][akq + 1][ar] = ah_; AsL[0][akq + 1][ar] = al_;
        tf32_split_f(av.z, ah_, al_); AsH[0][akq + 2][ar] = ah_; AsL[0][akq + 2][ar] = al_;
        tf32_split_f(av.w, ah_, al_); AsH[0][akq + 3][ar] = ah_; AsL[0][akq + 3][ar] = al_;
        float4 hv, lv;
        tf32_split_f(bv.x, hv.x, lv.x);
        tf32_split_f(bv.y, hv.y, lv.y);
        tf32_split_f(bv.z, hv.z, lv.z);
        tf32_split_f(bv.w, hv.w, lv.w);
        *(float4*)&BsH[0][bk][bnq] = hv;
        *(float4*)&BsL[0][bk][bnq] = lv;
    }
    __syncthreads();

    int p = 0;
#pragma unroll
    for (int s = 0; s < 16; s++) {
        if (s < 15) {
            int k0 = (s + 1) * 8;
            av = make_float4(0.f, 0.f, 0.f, 0.f);
            if (gr < M) av = *(const float4*)&A[(long)gr * IN_CH + k0 + akq];
            bv = *(const float4*)&B[(long)(k0 + bk) * C1 + colBase + bnq];
        }
        {
            unsigned ah[2][4], al[2][4];
#pragma unroll
            for (int im = 0; im < 2; im++) {
                int mb = warpM * 32 + im * 16;
                ah[im][0] = __float_as_uint(AsH[p][c][mb + r]);
                ah[im][1] = __float_as_uint(AsH[p][c][mb + 8 + r]);
                ah[im][2] = __float_as_uint(AsH[p][4 + c][mb + r]);
                ah[im][3] = __float_as_uint(AsH[p][4 + c][mb + 8 + r]);
                al[im][0] = __float_as_uint(AsL[p][c][mb + r]);
                al[im][1] = __float_as_uint(AsL[p][c][mb + 8 + r]);
                al[im][2] = __float_as_uint(AsL[p][4 + c][mb + r]);
                al[im][3] = __float_as_uint(AsL[p][4 + c][mb + 8 + r]);
            }
            unsigned bh[8][2], bl[8][2];
#pragma unroll
            for (int in = 0; in < 8; in++) {
                int nb = warpN * 64 + in * 8 + r;
                bh[in][0] = __float_as_uint(BsH[p][c][nb]);
                bh[in][1] = __float_as_uint(BsH[p][4 + c][nb]);
                bl[in][0] = __float_as_uint(BsL[p][c][nb]);
                bl[in][1] = __float_as_uint(BsL[p][4 + c][nb]);
            }
#pragma unroll
            for (int im = 0; im < 2; im++)
#pragma unroll
                for (int in = 0; in < 8; in++) {
                    mma_tf32(acc[im][in], al[im], bh[in]);
                    mma_tf32(acc[im][in], ah[im], bl[in]);
                    mma_tf32(acc[im][in], ah[im], bh[in]);
                }
        }
        if (s < 15) {
            p ^= 1;
            float ah_, al_;
            tf32_split_f(av.x, ah_, al_); AsH[p][akq + 0][ar] = ah_; AsL[p][akq + 0][ar] = al_;
            tf32_split_f(av.y, ah_, al_); AsH[p][akq + 1][ar] = ah_; AsL[p][akq + 1][ar] = al_;
            tf32_split_f(av.z, ah_, al_); AsH[p][akq + 2][ar] = ah_; AsL[p][akq + 2][ar] = al_;
            tf32_split_f(av.w, ah_, al_); AsH[p][akq + 3][ar] = ah_; AsL[p][akq + 3][ar] = al_;
            float4 hv, lv;
            tf32_split_f(bv.x, hv.x, lv.x);
            tf32_split_f(bv.y, hv.y, lv.y);
            tf32_split_f(bv.z, hv.z, lv.z);
            tf32_split_f(bv.w, hv.w, lv.w);
            *(float4*)&BsH[p][bk][bnq] = hv;
            *(float4*)&BsL[p][bk][bnq] = lv;
            __syncthreads();
        }
    }

    // epilogue: fp32 C + fp16 mirror
#pragma unroll
    for (int im = 0; im < 2; im++) {
        int row0 = rowBase + warpM * 32 + im * 16 + r;
        int row1 = row0 + 8;
#pragma unroll
        for (int in = 0; in < 8; in++) {
            int col = colBase + warpN * 64 + in * 8 + 2 * c;
            if (row0 < M) {
                float2 v = make_float2(acc[im][in][0], acc[im][in][1]);
                *(float2*)&C[(long)row0 * C1 + col] = v;
                *(__half2*)&g_xp1h[(long)row0 * C1 + col] = __float22half2_rn(v);
            }
            if (row1 < M) {
                float2 v = make_float2(acc[im][in][2], acc[im][in][3]);
                *(float2*)&C[(long)row1 * C1 + col] = v;
                *(__half2*)&g_xp1h[(long)row1 * C1 + col] = __float22half2_rn(v);
            }
        }
    }
}

// ============ GEMM2 (tc tf32x3): C[M,40] = A[M,256] @ B[256,40] =============
__global__ __launch_bounds__(256) void sgemm2_tc_kernel(const float* __restrict__ A,
                                                        const float* __restrict__ B,
                                                        float* __restrict__ C, int M) {
    __shared__ __align__(16) float As[2][16][PAD];
    __shared__ float BsH[2][16][40];
    __shared__ float BsL[2][16][40];

    const int tid  = threadIdx.x;
    const int wid  = tid >> 5;
    const int lane = tid & 31;
    const int rowBase = blockIdx.x * 128;
    const int r = lane >> 2;
    const int c = lane & 3;

    float acc[5][4];
#pragma unroll
    for (int j = 0; j < 5; j++)
#pragma unroll
        for (int q = 0; q < 4; q++) acc[j][q] = 0.0f;

    float4 avs[2];
    float  bsc[3];

#pragma unroll
    for (int t = 0; t < 2; t++) {
        int q = tid + t * 256;
        int ar = q >> 2, akq = q & 3;
        int gr = rowBase + ar;
        avs[t] = make_float4(0.f, 0.f, 0.f, 0.f);
        if (gr < M) avs[t] = *(const float4*)&A[(long)gr * C1 + akq * 4];
    }
#pragma unroll
    for (int t = 0; t < 3; t++) {
        int idx = tid + t * 256;
        bsc[t] = (idx < 16 * 40) ? B[(long)(idx / 40) * OUT_CH + idx % 40] : 0.f;
    }
#pragma unroll
    for (int t = 0; t < 2; t++) {
        int q = tid + t * 256;
        int ar = q >> 2, akq = q & 3;
        As[0][akq * 4 + 0][ar] = avs[t].x;
        As[0][akq * 4 + 1][ar] = avs[t].y;
        As[0][akq * 4 + 2][ar] = avs[t].z;
        As[0][akq * 4 + 3][ar] = avs[t].w;
    }
#pragma unroll
    for (int t = 0; t < 3; t++) {
        int idx = tid + t * 256;
        if (idx < 16 * 40) {
            float h_, l_;
            tf32_split_f(bsc[t], h_, l_);
            BsH[0][idx / 40][idx % 40] = h_;
            BsL[0][idx / 40][idx % 40] = l_;
        }
    }
    __syncthreads();

    int p = 0;
#pragma unroll
    for (int s = 0; s < 16; s++) {
        if (s < 15) {
            int k0 = (s + 1) * 16;
#pragma unroll
            for (int t = 0; t < 2; t++) {
                int q = tid + t * 256;
                int ar = q >> 2, akq = q & 3;
                int gr = rowBase + ar;
                avs[t] = make_float4(0.f, 0.f, 0.f, 0.f);
                if (gr < M) avs[t] = *(const float4*)&A[(long)gr * C1 + k0 + akq * 4];
            }
#pragma unroll
            for (int t = 0; t < 3; t++) {
                int idx = tid + t * 256;
                bsc[t] = (idx < 16 * 40) ? B[(long)(k0 + idx / 40) * OUT_CH + idx % 40] : 0.f;
            }
        }
#pragma unroll
        for (int kk = 0; kk < 16; kk += 8) {
            unsigned ah[4], al[4];
            {
                int mb = wid * 16;
                tf32_split(As[p][kk + c][mb + r],         ah[0], al[0]);
                tf32_split(As[p][kk + c][mb + 8 + r],     ah[1], al[1]);
                tf32_split(As[p][kk + 4 + c][mb + r],     ah[2], al[2]);
                tf32_split(As[p][kk + 4 + c][mb + 8 + r], ah[3], al[3]);
            }
#pragma unroll
            for (int in = 0; in < 5; in++) {
                int nb = in * 8 + r;
                unsigned bh[2], bl[2];
                bh[0] = __float_as_uint(BsH[p][kk + c][nb]);
                bh[1] = __float_as_uint(BsH[p][kk + 4 + c][nb]);
                bl[0] = __float_as_uint(BsL[p][kk + c][nb]);
                bl[1] = __float_as_uint(BsL[p][kk + 4 + c][nb]);
                mma_tf32(acc[in], al, bh);
                mma_tf32(acc[in], ah, bl);
                mma_tf32(acc[in], ah, bh);
            }
        }
        if (s < 15) {
            p ^= 1;
#pragma unroll
            for (int t = 0; t < 2; t++) {
                int q = tid + t * 256;
                int ar = q >> 2, akq = q & 3;
                As[p][akq * 4 + 0][ar] = avs[t].x;
                As[p][akq * 4 + 1][ar] = avs[t].y;
                As[p][akq * 4 + 2][ar] = avs[t].z;
                As[p][akq * 4 + 3][ar] = avs[t].w;
            }
#pragma unroll
            for (int t = 0; t < 3; t++) {
                int idx = tid + t * 256;
                if (idx < 16 * 40) {
                    float h_, l_;
                    tf32_split_f(bsc[t], h_, l_);
                    BsH[p][idx / 40][idx % 40] = h_;
                    BsL[p][idx / 40][idx % 40] = l_;
                }
            }
            __syncthreads();
        }
    }

    {
        int row0 = rowBase + wid * 16 + r;
        int row1 = row0 + 8;
#pragma unroll
        for (int in = 0; in < 5; in++) {
            int col = in * 8 + 2 * c;
            if (row0 < M)
                *(float2*)&C[(long)row0 * OUT_CH + col] = make_float2(acc[in][0], acc[in][1]);
            if (row1 < M)
                *(float2*)&C[(long)row1 * OUT_CH + col] = make_float2(acc[in][2], acc[in][3]);
        }
    }
}

// ---------------- attention coefficients, layer 1 (warp per node) -----------
__global__ void attn1_kernel(const float* __restrict__ att_src,
                             const float* __restrict__ att_dst) {
    int warp = (blockIdx.x * blockDim.x + threadIdx.x) >> 5;
    int lane = threadIdx.x & 31;
    if (warp >= N_NODES) return;
    const float* xp = &g_xp1[(long)warp * C1];
#pragma unroll
    for (int it = 0; it < 8; it++) {
        int c = it * 32 + lane;
        float v = xp[c];
        float ps = v * att_src[c];
        float pd = v * att_dst[c];
#pragma unroll
        for (int o = 16; o > 0; o >>= 1) {
            ps += __shfl_xor_sync(0xffffffffu, ps, o);
            pd += __shfl_xor_sync(0xffffffffu, pd, o);
        }
        if (lane == 0) {
            g_as1[warp * 8 + it] = ps;
            g_ad1[warp * 8 + it] = pd;
        }
    }
}

// ------- layer-1 aggregation: warp per dst node, fp16 gather, no atomics ----
__global__ __launch_bounds__(256) void agg1_kernel(const float* __restrict__ b1) {
    int n = (blockIdx.x * blockDim.x + threadIdx.x) >> 5;
    int lane = threadIdx.x & 31;
    if (n >= N_NODES) return;
    const int start = g_rowstart[n];
    const int end   = g_rowstart[n + 1];

    const int h   = lane & 7;
    const int grp = lane >> 3;
    const float adv = g_ad1[n * 8 + h];

    // pass 1: per-head max (every lane ends with max for head = lane&7)
    float m = -INFINITY;
    for (int i = start + grp; i < end; i += 4) {
        int s = g_csrc[i];
        m = fmaxf(m, leaky(g_as1[s * 8 + h] + adv));
    }
    m = fmaxf(m, __shfl_xor_sync(0xffffffffu, m, 8));
    m = fmaxf(m, __shfl_xor_sync(0xffffffffu, m, 16));

    // pass 2: exp + fp16-gather weighted accumulate
    // lane covers channels c4*64 + 2*lane + {0,1}; head = c4*2 + (lane>>4)
    float2 acc[4];
#pragma unroll
    for (int q = 0; q < 4; q++) acc[q] = make_float2(0.f, 0.f);
    float z = 0.f;
    const int hsel0 = (lane >> 4);
    for (int i = start; i < end; i++) {
        int s = g_csrc[i];
        float p = 0.f;
        if (lane < 8) {
            p = __expf(leaky(g_as1[s * 8 + lane] + adv) - m);
            z += p;
        }
        const __half2* xs = (const __half2*)&g_xp1h[(long)s * C1];
#pragma unroll
        for (int q = 0; q < 4; q++) {
            __half2 v = xs[q * 32 + lane];
            float2 f = __half22float2(v);
            float ph = __shfl_sync(0xffffffffu, p, q * 2 + hsel0);
            acc[q].x += ph * f.x;
            acc[q].y += ph * f.y;
        }
    }

    // finalize: divide, bias, relu -> g_h
    float* hd = &g_h[(long)n * C1];
#pragma unroll
    for (int q = 0; q < 4; q++) {
        float zh = __shfl_sync(0xffffffffu, z, q * 2 + hsel0);
        float zi = 1.0f / (zh + 1e-16f);
        int ch = q * 64 + 2 * lane;
        float2 o;
        o.x = fmaxf(acc[q].x * zi + b1[ch], 0.f);
        o.y = fmaxf(acc[q].y * zi + b1[ch + 1], 0.f);
        *(float2*)&hd[ch] = o;
    }
}

// ---------------- attention coefficients, layer 2 (warp per node) -----------
__global__ void attn2_kernel(const float* __restrict__ att_src,
                             const float* __restrict__ att_dst) {
    int warp = (blockIdx.x * blockDim.x + threadIdx.x) >> 5;
    int lane = threadIdx.x & 31;
    if (warp >= N_NODES) return;
    const float* xp = &g_xp2[(long)warp * OUT_CH];
    float v = xp[lane];
    float s = v * att_src[lane];
    float d = v * att_dst[lane];
    if (lane < 8) {
        float v2 = xp[32 + lane];
        s += v2 * att_src[32 + lane];
        d += v2 * att_dst[32 + lane];
    }
#pragma unroll
    for (int o = 16; o > 0; o >>= 1) {
        s += __shfl_xor_sync(0xffffffffu, s, o);
        d += __shfl_xor_sync(0xffffffffu, d, o);
    }
    if (lane == 0) { g_as2[warp] = s; g_ad2[warp] = d; }
}

// ---------- layer-2 aggregation + log_softmax: warp per dst node ------------
__global__ __launch_bounds__(256) void agg2_kernel(const float* __restrict__ b2,
                                                   float* __restrict__ out) {
    int n = (blockIdx.x * blockDim.x + threadIdx.x) >> 5;
    int lane = threadIdx.x & 31;
    if (n >= N_NODES) return;
    const int start = g_rowstart[n];
    const int end   = g_rowstart[n + 1];
    const float adn = g_ad2[n];

    float m = -INFINITY;
    for (int i = start + lane; i < end; i += 32)
        m = fmaxf(m, leaky(g_as2[g_csrc[i]] + adn));
#pragma unroll
    for (int o = 16; o > 0; o >>= 1)
        m = fmaxf(m, __shfl_xor_sync(0xffffffffu, m, o));

    float a0 = 0.f, a1 = 0.f, z = 0.f;
    for (int i = start; i < end; i++) {
        int s = g_csrc[i];
        float p = __expf(leaky(g_as2[s] + adn) - m);
        z += p;
        const float* xs = &g_xp2[(long)s * OUT_CH];
        a0 += p * xs[lane];
        if (lane < 8) a1 += p * xs[32 + lane];
    }
    float zi = 1.0f / (z + 1e-16f);

    float x1 = a0 * zi + b2[lane];
    float x2 = (lane < 8) ? (a1 * zi + b2[32 + lane]) : -INFINITY;
    float mx = fmaxf(x1, x2);
#pragma unroll
    for (int o = 16; o > 0; o >>= 1) mx = fmaxf(mx, __shfl_xor_sync(0xffffffffu, mx, o));
    float se = __expf(x1 - mx) + ((lane < 8) ? __expf(x2 - mx) : 0.0f);
#pragma unroll
    for (int o = 16; o > 0; o >>= 1) se += __shfl_xor_sync(0xffffffffu, se, o);
    float lse = mx + logf(se);
    out[(long)n * OUT_CH + lane] = x1 - lse;
    if (lane < 8) out[(long)n * OUT_CH + 32 + lane] = x2 - lse;
}

// ---------------- launch ----------------------------------------------------
extern "C" void kernel_launch(void* const* d_in, const int* in_sizes, int n_in,
                              void* d_out, int out_size) {
    const float* x        = (const float*)d_in[0];
    const int*   ei       = (const int*)d_in[1];
    const float* W1       = (const float*)d_in[2];
    const float* att_src1 = (const float*)d_in[3];
    const float* att_dst1 = (const float*)d_in[4];
    const float* b1       = (const float*)d_in[5];
    const float* W2       = (const float*)d_in[6];
    const float* att_src2 = (const float*)d_in[7];
    const float* att_dst2 = (const float*)d_in[8];
    const float* b2       = (const float*)d_in[9];
    float*       out      = (float*)d_out;

    float* xp1 = nullptr; float* h = nullptr; float* xp2 = nullptr;
    cudaGetSymbolAddress((void**)&xp1, g_xp1);
    cudaGetSymbolAddress((void**)&h,   g_h);
    cudaGetSymbolAddress((void**)&xp2, g_xp2);

    // CSR build (shared by both layers)
    zero_deg_kernel<<<(N_NODES + 255) / 256, 256>>>();
    hist_kernel<<<(ET + 255) / 256, 256>>>(ei);
    scan_kernel<<<1, 1024>>>();
    scatter_kernel<<<(ET + 255) / 256, 256>>>(ei);

    // layer 1
    {
        dim3 grid(C1 / 128, (N_NODES + 127) / 128);
        sgemm1_tc_kernel<<<grid, 256>>>(x, W1, xp1, N_NODES);
    }
    attn1_kernel<<<(N_NODES * 32 + 255) / 256, 256>>>(att_src1, att_dst1);
    agg1_kernel<<<(N_NODES * 32 + 255) / 256, 256>>>(b1);

    // layer 2
    sgemm2_tc_kernel<<<(N_NODES + 127) / 128, 256>>>(h, W2, xp2, N_NODES);
    attn2_kernel<<<(N_NODES * 32 + 255) / 256, 256>>>(att_src2, att_dst2);
    agg2_kernel<<<(N_NODES * 32 + 255) / 256, 256>>>(b2, out);
}

// round 11
// speedup vs baseline: 2.0152x; 1.1077x over previous
#include <cuda_runtime.h>
#include <cuda_fp16.h>
#include <math.h>

#define N_NODES 100000
#define E_EDGES 800000
#define ET (E_EDGES + N_NODES)   // edges + self loops = 900000
#define IN_CH 128
#define HID 32
#define HEADS 8
#define C1 (HEADS * HID)          // 256
#define OUT_CH 40
#define NEG_SLOPE 0.2f

// ---------------- scratch (device globals; no allocation allowed) ----------
__device__ float  g_xp1[N_NODES * C1];
__device__ __half g_xp1h[N_NODES * C1];   // fp16 mirror for the edge gather
__device__ float  g_h[N_NODES * C1];
__device__ float  g_xp2[N_NODES * OUT_CH];
__device__ float  g_as1[N_NODES * HEADS];
__device__ float  g_ad1[N_NODES * HEADS];
__device__ float  g_as2[N_NODES];
__device__ float  g_ad2[N_NODES];

__device__ int g_deg[N_NODES];
__device__ int g_rowstart[N_NODES + 1];
__device__ int g_cursor[N_NODES];
__device__ int g_csrc[ET];

__device__ __forceinline__ float leaky(float x) {
    return x > 0.0f ? x : NEG_SLOPE * x;
}

// ================= CSR build (+ zero of attn accumulators) ==================
__global__ void zero_kernel() {
    int i = blockIdx.x * blockDim.x + threadIdx.x;
    if (i < N_NODES) {
        g_deg[i] = 0;
#pragma unroll
        for (int h = 0; h < 8; h++) {
            g_as1[i * 8 + h] = 0.0f;
            g_ad1[i * 8 + h] = 0.0f;
        }
    }
}

__global__ void hist_kernel(const int* __restrict__ ei) {
    int e = blockIdx.x * blockDim.x + threadIdx.x;
    if (e >= ET) return;
    int dst = (e < E_EDGES) ? ei[E_EDGES + e] : e - E_EDGES;
    atomicAdd(&g_deg[dst], 1);
}

__global__ void scan_kernel() {
    __shared__ int sums[1024];
    const int t = threadIdx.x;
    const int CH = (N_NODES + 1023) / 1024;
    int lo = t * CH;
    int hi = lo + CH; if (hi > N_NODES) hi = N_NODES;
    int s = 0;
    for (int i = lo; i < hi; i++) s += g_deg[i];
    sums[t] = s;
    __syncthreads();
    for (int o = 1; o < 1024; o <<= 1) {
        int u = (t >= o) ? sums[t - o] : 0;
        __syncthreads();
        sums[t] += u;
        __syncthreads();
    }
    int run = sums[t] - s;
    for (int i = lo; i < hi; i++) {
        g_rowstart[i] = run;
        g_cursor[i]   = run;
        run += g_deg[i];
    }
    if (t == 0) g_rowstart[N_NODES] = ET;
}

__global__ void scatter_kernel(const int* __restrict__ ei) {
    int e = blockIdx.x * blockDim.x + threadIdx.x;
    if (e >= ET) return;
    int src, dst;
    if (e < E_EDGES) { src = ei[e]; dst = ei[E_EDGES + e]; }
    else             { src = dst = e - E_EDGES; }
    int pos = atomicAdd(&g_cursor[dst], 1);
    g_csrc[pos] = src;
}

// ================= tf32 helpers =============================================
__device__ __forceinline__ unsigned tf32_of(float x) {
    unsigned r;
    asm("cvt.rna.tf32.f32 %0, %1;" : "=r"(r) : "f"(x));
    return r;
}
__device__ __forceinline__ void tf32_split(float x, unsigned& hi, unsigned& lo) {
    hi = tf32_of(x);
    float lo_f = x - __uint_as_float(hi);
    lo = tf32_of(lo_f);
}
__device__ __forceinline__ void tf32_split_f(float x, float& hi, float& lo) {
    unsigned h, l;
    tf32_split(x, h, l);
    hi = __uint_as_float(h);
    lo = __uint_as_float(l);
}
__device__ __forceinline__ void mma_tf32(float* d, const unsigned* a, const unsigned* b) {
    asm volatile(
        "mma.sync.aligned.m16n8k8.row.col.f32.tf32.tf32.f32 "
        "{%0,%1,%2,%3}, {%4,%5,%6,%7}, {%8,%9}, {%0,%1,%2,%3};"
        : "+f"(d[0]), "+f"(d[1]), "+f"(d[2]), "+f"(d[3])
        : "r"(a[0]), "r"(a[1]), "r"(a[2]), "r"(a[3]), "r"(b[0]), "r"(b[1]));
}
__device__ __forceinline__ float quad_reduce(float v) {
    v += __shfl_xor_sync(0xffffffffu, v, 1);
    v += __shfl_xor_sync(0xffffffffu, v, 2);
    return v;
}

#define PAD 136

// ============ GEMM1 (tc tf32x3) + fused attn1 dots ==========================
__global__ __launch_bounds__(256) void sgemm1_tc_kernel(const float* __restrict__ A,
                                                        const float* __restrict__ B,
                                                        float* __restrict__ C,
                                                        const float* __restrict__ att_src,
                                                        const float* __restrict__ att_dst,
                                                        int M) {
    __shared__ __align__(16) float AsH[2][8][PAD];
    __shared__ __align__(16) float AsL[2][8][PAD];
    __shared__ __align__(16) float BsH[2][8][PAD];
    __shared__ __align__(16) float BsL[2][8][PAD];

    const int tid  = threadIdx.x;
    const int wid  = tid >> 5;
    const int lane = tid & 31;
    const int warpM = wid & 3;
    const int warpN = wid >> 2;
    const int rowBase = blockIdx.y * 128;
    const int colBase = blockIdx.x * 128;

    const int r = lane >> 2;
    const int c = lane & 3;

    float acc[2][8][4];
#pragma unroll
    for (int i = 0; i < 2; i++)
#pragma unroll
        for (int j = 0; j < 8; j++)
#pragma unroll
            for (int q = 0; q < 4; q++) acc[i][j][q] = 0.0f;

    const int ar  = tid >> 1;
    const int akq = (tid & 1) * 4;
    const int bk  = tid >> 5;
    const int bnq = (tid & 31) * 4;
    const int gr  = rowBase + ar;

    float4 av, bv;

    av = make_float4(0.f, 0.f, 0.f, 0.f);
    if (gr < M) av = *(const float4*)&A[(long)gr * IN_CH + akq];
    bv = *(const float4*)&B[(long)bk * C1 + colBase + bnq];
    {
        float ah_, al_;
        tf32_split_f(av.x, ah_, al_); AsH[0][akq + 0][ar] = ah_; AsL[0][akq + 0][ar] = al_;
        tf32_split_f(av.y, ah_, al_); AsH[0][akq + 1][ar] = ah_; AsL[0][akq + 1][ar] = al_;
        tf32_split_f(av.z, ah_, al_); AsH[0][akq + 2][ar] = ah_; AsL[0][akq + 2][ar] = al_;
        tf32_split_f(av.w, ah_, al_); AsH[0][akq + 3][ar] = ah_; AsL[0][akq + 3][ar] = al_;
        float4 hv, lv;
        tf32_split_f(bv.x, hv.x, lv.x);
        tf32_split_f(bv.y, hv.y, lv.y);
        tf32_split_f(bv.z, hv.z, lv.z);
        tf32_split_f(bv.w, hv.w, lv.w);
        *(float4*)&BsH[0][bk][bnq] = hv;
        *(float4*)&BsL[0][bk][bnq] = lv;
    }
    __syncthreads();

    int p = 0;
#pragma unroll
    for (int s = 0; s < 16; s++) {
        if (s < 15) {
            int k0 = (s + 1) * 8;
            av = make_float4(0.f, 0.f, 0.f, 0.f);
            if (gr < M) av = *(const float4*)&A[(long)gr * IN_CH + k0 + akq];
            bv = *(const float4*)&B[(long)(k0 + bk) * C1 + colBase + bnq];
        }
        {
            unsigned ah[2][4], al[2][4];
#pragma unroll
            for (int im = 0; im < 2; im++) {
                int mb = warpM * 32 + im * 16;
                ah[im][0] = __float_as_uint(AsH[p][c][mb + r]);
                ah[im][1] = __float_as_uint(AsH[p][c][mb + 8 + r]);
                ah[im][2] = __float_as_uint(AsH[p][4 + c][mb + r]);
                ah[im][3] = __float_as_uint(AsH[p][4 + c][mb + 8 + r]);
                al[im][0] = __float_as_uint(AsL[p][c][mb + r]);
                al[im][1] = __float_as_uint(AsL[p][c][mb + 8 + r]);
                al[im][2] = __float_as_uint(AsL[p][4 + c][mb + r]);
                al[im][3] = __float_as_uint(AsL[p][4 + c][mb + 8 + r]);
            }
            unsigned bh[8][2], bl[8][2];
#pragma unroll
            for (int in = 0; in < 8; in++) {
                int nb = warpN * 64 + in * 8 + r;
                bh[in][0] = __float_as_uint(BsH[p][c][nb]);
                bh[in][1] = __float_as_uint(BsH[p][4 + c][nb]);
                bl[in][0] = __float_as_uint(BsL[p][c][nb]);
                bl[in][1] = __float_as_uint(BsL[p][4 + c][nb]);
            }
#pragma unroll
            for (int im = 0; im < 2; im++)
#pragma unroll
                for (int in = 0; in < 8; in++) {
                    mma_tf32(acc[im][in], al[im], bh[in]);
                    mma_tf32(acc[im][in], ah[im], bl[in]);
                    mma_tf32(acc[im][in], ah[im], bh[in]);
                }
        }
        if (s < 15) {
            p ^= 1;
            float ah_, al_;
            tf32_split_f(av.x, ah_, al_); AsH[p][akq + 0][ar] = ah_; AsL[p][akq + 0][ar] = al_;
            tf32_split_f(av.y, ah_, al_); AsH[p][akq + 1][ar] = ah_; AsL[p][akq + 1][ar] = al_;
            tf32_split_f(av.z, ah_, al_); AsH[p][akq + 2][ar] = ah_; AsL[p][akq + 2][ar] = al_;
            tf32_split_f(av.w, ah_, al_); AsH[p][akq + 3][ar] = ah_; AsL[p][akq + 3][ar] = al_;
            float4 hv, lv;
            tf32_split_f(bv.x, hv.x, lv.x);
            tf32_split_f(bv.y, hv.y, lv.y);
            tf32_split_f(bv.z, hv.z, lv.z);
            tf32_split_f(bv.w, hv.w, lv.w);
            *(float4*)&BsH[p][bk][bnq] = hv;
            *(float4*)&BsL[p][bk][bnq] = lv;
            __syncthreads();
        }
    }

    // epilogue: fp32 C + fp16 mirror + fused attention dots
#pragma unroll
    for (int im = 0; im < 2; im++) {
        int row0 = rowBase + warpM * 32 + im * 16 + r;
        int row1 = row0 + 8;
        float s0[2] = {0.f, 0.f}, d0[2] = {0.f, 0.f};   // row0: head pair
        float s1[2] = {0.f, 0.f}, d1[2] = {0.f, 0.f};   // row1
#pragma unroll
        for (int in = 0; in < 8; in++) {
            int col = colBase + warpN * 64 + in * 8 + 2 * c;
            float w0 = att_src[col], w1 = att_src[col + 1];
            float v0 = att_dst[col], v1 = att_dst[col + 1];
            int hp = in >> 2;
            s0[hp] += acc[im][in][0] * w0 + acc[im][in][1] * w1;
            d0[hp] += acc[im][in][0] * v0 + acc[im][in][1] * v1;
            s1[hp] += acc[im][in][2] * w0 + acc[im][in][3] * w1;
            d1[hp] += acc[im][in][2] * v0 + acc[im][in][3] * v1;
            if (row0 < M) {
                float2 v = make_float2(acc[im][in][0], acc[im][in][1]);
                *(float2*)&C[(long)row0 * C1 + col] = v;
                *(__half2*)&g_xp1h[(long)row0 * C1 + col] = __float22half2_rn(v);
            }
            if (row1 < M) {
                float2 v = make_float2(acc[im][in][2], acc[im][in][3]);
                *(float2*)&C[(long)row1 * C1 + col] = v;
                *(__half2*)&g_xp1h[(long)row1 * C1 + col] = __float22half2_rn(v);
            }
        }
#pragma unroll
        for (int hp = 0; hp < 2; hp++) {
            s0[hp] = quad_reduce(s0[hp]); d0[hp] = quad_reduce(d0[hp]);
            s1[hp] = quad_reduce(s1[hp]); d1[hp] = quad_reduce(d1[hp]);
        }
        if (c == 0) {
            int hbase = (colBase >> 5) + warpN * 2;
#pragma unroll
            for (int hp = 0; hp < 2; hp++) {
                if (row0 < M) {
                    atomicAdd(&g_as1[row0 * 8 + hbase + hp], s0[hp]);
                    atomicAdd(&g_ad1[row0 * 8 + hbase + hp], d0[hp]);
                }
                if (row1 < M) {
                    atomicAdd(&g_as1[row1 * 8 + hbase + hp], s1[hp]);
                    atomicAdd(&g_ad1[row1 * 8 + hbase + hp], d1[hp]);
                }
            }
        }
    }
}

// ============ GEMM2 (tc tf32x3) + fused attn2 dots ==========================
__global__ __launch_bounds__(256) void sgemm2_tc_kernel(const float* __restrict__ A,
                                                        const float* __restrict__ B,
                                                        float* __restrict__ C,
                                                        const float* __restrict__ att_src,
                                                        const float* __restrict__ att_dst,
                                                        int M) {
    __shared__ __align__(16) float As[2][16][PAD];
    __shared__ float BsH[2][16][40];
    __shared__ float BsL[2][16][40];

    const int tid  = threadIdx.x;
    const int wid  = tid >> 5;
    const int lane = tid & 31;
    const int rowBase = blockIdx.x * 128;
    const int r = lane >> 2;
    const int c = lane & 3;

    float acc[5][4];
#pragma unroll
    for (int j = 0; j < 5; j++)
#pragma unroll
        for (int q = 0; q < 4; q++) acc[j][q] = 0.0f;

    float4 avs[2];
    float  bsc[3];

#pragma unroll
    for (int t = 0; t < 2; t++) {
        int q = tid + t * 256;
        int ar = q >> 2, akq = q & 3;
        int gr = rowBase + ar;
        avs[t] = make_float4(0.f, 0.f, 0.f, 0.f);
        if (gr < M) avs[t] = *(const float4*)&A[(long)gr * C1 + akq * 4];
    }
#pragma unroll
    for (int t = 0; t < 3; t++) {
        int idx = tid + t * 256;
        bsc[t] = (idx < 16 * 40) ? B[(long)(idx / 40) * OUT_CH + idx % 40] : 0.f;
    }
#pragma unroll
    for (int t = 0; t < 2; t++) {
        int q = tid + t * 256;
        int ar = q >> 2, akq = q & 3;
        As[0][akq * 4 + 0][ar] = avs[t].x;
        As[0][akq * 4 + 1][ar] = avs[t].y;
        As[0][akq * 4 + 2][ar] = avs[t].z;
        As[0][akq * 4 + 3][ar] = avs[t].w;
    }
#pragma unroll
    for (int t = 0; t < 3; t++) {
        int idx = tid + t * 256;
        if (idx < 16 * 40) {
            float h_, l_;
            tf32_split_f(bsc[t], h_, l_);
            BsH[0][idx / 40][idx % 40] = h_;
            BsL[0][idx / 40][idx % 40] = l_;
        }
    }
    __syncthreads();

    int p = 0;
#pragma unroll
    for (int s = 0; s < 16; s++) {
        if (s < 15) {
            int k0 = (s + 1) * 16;
#pragma unroll
            for (int t = 0; t < 2; t++) {
                int q = tid + t * 256;
                int ar = q >> 2, akq = q & 3;
                int gr = rowBase + ar;
                avs[t] = make_float4(0.f, 0.f, 0.f, 0.f);
                if (gr < M) avs[t] = *(const float4*)&A[(long)gr * C1 + k0 + akq * 4];
            }
#pragma unroll
            for (int t = 0; t < 3; t++) {
                int idx = tid + t * 256;
                bsc[t] = (idx < 16 * 40) ? B[(long)(k0 + idx / 40) * OUT_CH + idx % 40] : 0.f;
            }
        }
#pragma unroll
        for (int kk = 0; kk < 16; kk += 8) {
            unsigned ah[4], al[4];
            {
                int mb = wid * 16;
                tf32_split(As[p][kk + c][mb + r],         ah[0], al[0]);
                tf32_split(As[p][kk + c][mb + 8 + r],     ah[1], al[1]);
                tf32_split(As[p][kk + 4 + c][mb + r],     ah[2], al[2]);
                tf32_split(As[p][kk + 4 + c][mb + 8 + r], ah[3], al[3]);
            }
#pragma unroll
            for (int in = 0; in < 5; in++) {
                int nb = in * 8 + r;
                unsigned bh[2], bl[2];
                bh[0] = __float_as_uint(BsH[p][kk + c][nb]);
                bh[1] = __float_as_uint(BsH[p][kk + 4 + c][nb]);
                bl[0] = __float_as_uint(BsL[p][kk + c][nb]);
                bl[1] = __float_as_uint(BsL[p][kk + 4 + c][nb]);
                mma_tf32(acc[in], al, bh);
                mma_tf32(acc[in], ah, bl);
                mma_tf32(acc[in], ah, bh);
            }
        }
        if (s < 15) {
            p ^= 1;
#pragma unroll
            for (int t = 0; t < 2; t++) {
                int q = tid + t * 256;
                int ar = q >> 2, akq = q & 3;
                As[p][akq * 4 + 0][ar] = avs[t].x;
                As[p][akq * 4 + 1][ar] = avs[t].y;
                As[p][akq * 4 + 2][ar] = avs[t].z;
                As[p][akq * 4 + 3][ar] = avs[t].w;
            }
#pragma unroll
            for (int t = 0; t < 3; t++) {
                int idx = tid + t * 256;
                if (idx < 16 * 40) {
                    float h_, l_;
                    tf32_split_f(bsc[t], h_, l_);
                    BsH[p][idx / 40][idx % 40] = h_;
                    BsL[p][idx / 40][idx % 40] = l_;
                }
            }
            __syncthreads();
        }
    }

    // epilogue: C + fused attn2 dots (full row per warp -> direct store)
    {
        int row0 = rowBase + wid * 16 + r;
        int row1 = row0 + 8;
        float s0 = 0.f, d0 = 0.f, s1 = 0.f, d1 = 0.f;
#pragma unroll
        for (int in = 0; in < 5; in++) {
            int col = in * 8 + 2 * c;
            float w0 = att_src[col], w1 = att_src[col + 1];
            float v0 = att_dst[col], v1 = att_dst[col + 1];
            s0 += acc[in][0] * w0 + acc[in][1] * w1;
            d0 += acc[in][0] * v0 + acc[in][1] * v1;
            s1 += acc[in][2] * w0 + acc[in][3] * w1;
            d1 += acc[in][2] * v0 + acc[in][3] * v1;
            if (row0 < M)
                *(float2*)&C[(long)row0 * OUT_CH + col] = make_float2(acc[in][0], acc[in][1]);
            if (row1 < M)
                *(float2*)&C[(long)row1 * OUT_CH + col] = make_float2(acc[in][2], acc[in][3]);
        }
        s0 = quad_reduce(s0); d0 = quad_reduce(d0);
        s1 = quad_reduce(s1); d1 = quad_reduce(d1);
        if (c == 0) {
            if (row0 < M) { g_as2[row0] = s0; g_ad2[row0] = d0; }
            if (row1 < M) { g_as2[row1] = s1; g_ad2[row1] = d1; }
        }
    }
}

// ------- layer-1 aggregation: warp per dst node, fp16 float4 gather ---------
__global__ __launch_bounds__(256) void agg1_kernel(const float* __restrict__ b1) {
    int n = (blockIdx.x * blockDim.x + threadIdx.x) >> 5;
    int lane = threadIdx.x & 31;
    if (n >= N_NODES) return;
    const int start = g_rowstart[n];
    const int end   = g_rowstart[n + 1];

    const int h   = lane & 7;
    const int grp = lane >> 3;
    const float adv = g_ad1[n * 8 + h];

    // pass 1: per-head max
    float m = -INFINITY;
    for (int i = start + grp; i < end; i += 4) {
        int s = g_csrc[i];
        m = fmaxf(m, leaky(g_as1[s * 8 + h] + adv));
    }
    m = fmaxf(m, __shfl_xor_sync(0xffffffffu, m, 8));
    m = fmaxf(m, __shfl_xor_sync(0xffffffffu, m, 16));

    // pass 2: exp + fp16 float4 gather (lane owns channels 8*lane..8*lane+7,
    // all within head lane>>2)
    float2 acc4[4];
#pragma unroll
    for (int q = 0; q < 4; q++) acc4[q] = make_float2(0.f, 0.f);
    float z = 0.f;
    const int hsel = lane >> 2;
    for (int i = start; i < end; i++) {
        int s = g_csrc[i];
        float p = 0.f;
        if (lane < 8) {
            p = __expf(leaky(g_as1[s * 8 + lane] + adv) - m);
            z += p;
        }
        float4 raw = *(const float4*)&g_xp1h[(long)s * C1 + 8 * lane];
        const __half2* hp = reinterpret_cast<const __half2*>(&raw);
        float ph = __shfl_sync(0xffffffffu, p, hsel);
#pragma unroll
        for (int q = 0; q < 4; q++) {
            float2 f = __half22float2(hp[q]);
            acc4[q].x += ph * f.x;
            acc4[q].y += ph * f.y;
        }
    }

    // finalize: divide, bias, relu -> g_h
    float zh = __shfl_sync(0xffffffffu, z, hsel);
    float zi = 1.0f / (zh + 1e-16f);
    int ch = 8 * lane;
    float4 o0, o1;
    o0.x = fmaxf(acc4[0].x * zi + b1[ch + 0], 0.f);
    o0.y = fmaxf(acc4[0].y * zi + b1[ch + 1], 0.f);
    o0.z = fmaxf(acc4[1].x * zi + b1[ch + 2], 0.f);
    o0.w = fmaxf(acc4[1].y * zi + b1[ch + 3], 0.f);
    o1.x = fmaxf(acc4[2].x * zi + b1[ch + 4], 0.f);
    o1.y = fmaxf(acc4[2].y * zi + b1[ch + 5], 0.f);
    o1.z = fmaxf(acc4[3].x * zi + b1[ch + 6], 0.f);
    o1.w = fmaxf(acc4[3].y * zi + b1[ch + 7], 0.f);
    float* hd = &g_h[(long)n * C1];
    *(float4*)&hd[ch]     = o0;
    *(float4*)&hd[ch + 4] = o1;
}

// ---------- layer-2 aggregation + log_softmax: warp per dst node ------------
__global__ __launch_bounds__(256) void agg2_kernel(const float* __restrict__ b2,
                                                   float* __restrict__ out) {
    int n = (blockIdx.x * blockDim.x + threadIdx.x) >> 5;
    int lane = threadIdx.x & 31;
    if (n >= N_NODES) return;
    const int start = g_rowstart[n];
    const int end   = g_rowstart[n + 1];
    const float adn = g_ad2[n];

    float m = -INFINITY;
    for (int i = start + lane; i < end; i += 32)
        m = fmaxf(m, leaky(g_as2[g_csrc[i]] + adn));
#pragma unroll
    for (int o = 16; o > 0; o >>= 1)
        m = fmaxf(m, __shfl_xor_sync(0xffffffffu, m, o));

    // lane < 10 owns channels 4*lane..4*lane+3
    float4 a = make_float4(0.f, 0.f, 0.f, 0.f);
    float z = 0.f;
    for (int i = start; i < end; i++) {
        int s = g_csrc[i];
        float p = __expf(leaky(g_as2[s] + adn) - m);
        z += p;
        if (lane < 10) {
            float4 xs = *(const float4*)&g_xp2[(long)s * OUT_CH + 4 * lane];
            a.x += p * xs.x; a.y += p * xs.y; a.z += p * xs.z; a.w += p * xs.w;
        }
    }
    float zi = 1.0f / (z + 1e-16f);

    float x0 = -INFINITY, x1 = -INFINITY, x2 = -INFINITY, x3 = -INFINITY;
    if (lane < 10) {
        int ch = 4 * lane;
        x0 = a.x * zi + b2[ch + 0];
        x1 = a.y * zi + b2[ch + 1];
        x2 = a.z * zi + b2[ch + 2];
        x3 = a.w * zi + b2[ch + 3];
    }
    float mx = fmaxf(fmaxf(x0, x1), fmaxf(x2, x3));
#pragma unroll
    for (int o = 16; o > 0; o >>= 1) mx = fmaxf(mx, __shfl_xor_sync(0xffffffffu, mx, o));
    float se = 0.f;
    if (lane < 10)
        se = __expf(x0 - mx) + __expf(x1 - mx) + __expf(x2 - mx) + __expf(x3 - mx);
#pragma unroll
    for (int o = 16; o > 0; o >>= 1) se += __shfl_xor_sync(0xffffffffu, se, o);
    float lse = mx + logf(se);
    if (lane < 10) {
        float4 o4 = make_float4(x0 - lse, x1 - lse, x2 - lse, x3 - lse);
        *(float4*)&out[(long)n * OUT_CH + 4 * lane] = o4;
    }
}

// ---------------- launch ----------------------------------------------------
extern "C" void kernel_launch(void* const* d_in, const int* in_sizes, int n_in,
                              void* d_out, int out_size) {
    const float* x        = (const float*)d_in[0];
    const int*   ei       = (const int*)d_in[1];
    const float* W1       = (const float*)d_in[2];
    const float* att_src1 = (const float*)d_in[3];
    const float* att_dst1 = (const float*)d_in[4];
    const float* b1       = (const float*)d_in[5];
    const float* W2       = (const float*)d_in[6];
    const float* att_src2 = (const float*)d_in[7];
    const float* att_dst2 = (const float*)d_in[8];
    const float* b2       = (const float*)d_in[9];
    float*       out      = (float*)d_out;

    float* xp1 = nullptr; float* h = nullptr; float* xp2 = nullptr;
    cudaGetSymbolAddress((void**)&xp1, g_xp1);
    cudaGetSymbolAddress((void**)&h,   g_h);
    cudaGetSymbolAddress((void**)&xp2, g_xp2);

    // CSR build (shared by both layers) + attn accumulator zero
    zero_kernel<<<(N_NODES + 255) / 256, 256>>>();
    hist_kernel<<<(ET + 255) / 256, 256>>>(ei);
    scan_kernel<<<1, 1024>>>();
    scatter_kernel<<<(ET + 255) / 256, 256>>>(ei);

    // layer 1 (attn1 fused into GEMM1 epilogue)
    {
        dim3 grid(C1 / 128, (N_NODES + 127) / 128);
        sgemm1_tc_kernel<<<grid, 256>>>(x, W1, xp1, att_src1, att_dst1, N_NODES);
    }
    agg1_kernel<<<(N_NODES * 32 + 255) / 256, 256>>>(b1);

    // layer 2 (attn2 fused into GEMM2 epilogue)
    sgemm2_tc_kernel<<<(N_NODES + 127) / 128, 256>>>(h, W2, xp2, att_src2, att_dst2, N_NODES);
    agg2_kernel<<<(N_NODES * 32 + 255) / 256, 256>>>(b2, out);
}